// round 2
// baseline (speedup 1.0000x reference)
#include <cuda_runtime.h>
#include <cuda_bf16.h>
#include <cstddef>
#include <cstdint>

// Problem constants
#define BB   256
#define SS   100
#define II   128
#define HH   1024
#define OO   128
#define LL   2
#define UU   1344
#define KK   4
#define NTOK (BB * SS)          // 25600
#define H4   (4 * HH)           // 4096
#define U2   (2 * UU)           // 2688

// ---------------------------------------------------------------------------
// Scratch: one __device__ array (no allocations allowed). ~743 MB.
// Layout (floats), with aliasing:
//  h     : NTOK*H          = 26,214,400
//  xn    : NTOK*H          (also FFN input "fn")
//  xc    : NTOK*H          (also yseq — xc consumed before scan writes yseq)
//  Wx    : NTOK*4H         = 104,857,600  (also gv [NTOK*2U] — Wx consumed
//                                          by scan before FFN writes gv;
//                                          act computed in-place in g half)
//  raw   : B*4H            = 1,048,576
//  state : 4*B*H           = 1,048,576     (y,c,n,m)
//  last  : B*H             = 262,144
#define SCRATCH_FLOATS 185860096ULL
__device__ float g_scratch[SCRATCH_FLOATS];

// ---------------------------------------------------------------------------
// Generic fp32 NT/NN tiled GEMM.
//   C[M,N] = A[M,K] * op(B)      op(B) = B^T if BT (B stored [N,K]),
//                                 else B stored [K,N]
// M % BM == 0, N % BN == 0, K % BK == 0, lda/ldb % 4 == 0 (guaranteed).
template<int BM, int BN, int BK, int TM, int TN, bool BT, bool ACC, bool BIAS>
__global__ void __launch_bounds__(256)
gemm_kernel(const float* __restrict__ A, int lda,
            const float* __restrict__ B, int ldb,
            float* __restrict__ C, int ldc,
            const float* __restrict__ bias,
            int K)
{
    constexpr int TX = BN / TN;
    constexpr int TY = BM / TM;
    constexpr int NT = TX * TY;

    __shared__ float As[BK][BM + 4];
    __shared__ float Bs[BK][BN + 4];

    const int tid = threadIdx.x;
    const int tx = tid % TX;
    const int ty = tid / TX;
    const long bm0 = (long)blockIdx.y * BM;
    const long bn0 = (long)blockIdx.x * BN;

    float acc[TM][TN];
#pragma unroll
    for (int i = 0; i < TM; i++)
#pragma unroll
        for (int j = 0; j < TN; j++) acc[i][j] = 0.f;

    for (int k0 = 0; k0 < K; k0 += BK) {
        // Load A tile (row-major [M,K]) -> As[k][m]
#pragma unroll
        for (int i = tid * 4; i < BM * BK; i += NT * 4) {
            int r  = i / BK;
            int kk = i % BK;
            float4 v = *(const float4*)(A + (bm0 + r) * (long)lda + (k0 + kk));
            As[kk + 0][r] = v.x;
            As[kk + 1][r] = v.y;
            As[kk + 2][r] = v.z;
            As[kk + 3][r] = v.w;
        }
        if (BT) {
            // B stored [N,K] -> Bs[k][n]
#pragma unroll
            for (int i = tid * 4; i < BN * BK; i += NT * 4) {
                int r  = i / BK;
                int kk = i % BK;
                float4 v = *(const float4*)(B + (bn0 + r) * (long)ldb + (k0 + kk));
                Bs[kk + 0][r] = v.x;
                Bs[kk + 1][r] = v.y;
                Bs[kk + 2][r] = v.z;
                Bs[kk + 3][r] = v.w;
            }
        } else {
            // B stored [K,N] -> Bs[k][n]
#pragma unroll
            for (int i = tid * 4; i < BK * BN; i += NT * 4) {
                int kk = i / BN;
                int c  = i % BN;
                float4 v = *(const float4*)(B + (long)(k0 + kk) * ldb + bn0 + c);
                *(float4*)&Bs[kk][c] = v;
            }
        }
        __syncthreads();

#pragma unroll
        for (int kk = 0; kk < BK; kk++) {
            float a[TM], b[TN];
#pragma unroll
            for (int i = 0; i < TM; i += 4)
                *(float4*)&a[i] = *(const float4*)&As[kk][ty * TM + i];
#pragma unroll
            for (int j = 0; j < TN; j += 4)
                *(float4*)&b[j] = *(const float4*)&Bs[kk][tx * TN + j];
#pragma unroll
            for (int i = 0; i < TM; i++)
#pragma unroll
                for (int j = 0; j < TN; j++)
                    acc[i][j] = fmaf(a[i], b[j], acc[i][j]);
        }
        __syncthreads();
    }

    // Epilogue
#pragma unroll
    for (int i = 0; i < TM; i++) {
        long row = bm0 + ty * TM + i;
#pragma unroll
        for (int j = 0; j < TN; j++) {
            long col = bn0 + tx * TN + j;
            float v = acc[i][j];
            if (BIAS) v += bias[col];
            long off = row * (long)ldc + col;
            if (ACC) v += C[off];
            C[off] = v;
        }
    }
}

// ---------------------------------------------------------------------------
// Block reduce (sum, sumsq) across 256 threads.
__device__ __forceinline__ void block_reduce2(float& s, float& ss)
{
    __shared__ float sh[16];
    int lane = threadIdx.x & 31;
    int wid  = threadIdx.x >> 5;
#pragma unroll
    for (int o = 16; o > 0; o >>= 1) {
        s  += __shfl_xor_sync(0xFFFFFFFFu, s,  o);
        ss += __shfl_xor_sync(0xFFFFFFFFu, ss, o);
    }
    if (lane == 0) { sh[wid] = s; sh[8 + wid] = ss; }
    __syncthreads();
    if (threadIdx.x < 32) {
        float a = (lane < 8) ? sh[lane]     : 0.f;
        float b = (lane < 8) ? sh[8 + lane] : 0.f;
#pragma unroll
        for (int o = 4; o > 0; o >>= 1) {
            a += __shfl_xor_sync(0xFFFFFFFFu, a, o);
            b += __shfl_xor_sync(0xFFFFFFFFu, b, o);
        }
        if (lane == 0) { sh[0] = a; sh[8] = b; }
    }
    __syncthreads();
    s  = sh[0];
    ss = sh[8];
}

// out[row] = LN(x[row]) * w        (weight-only LN, eps 1e-5, width 1024)
__global__ void ln_kernel(const float* __restrict__ x, size_t xs,
                          const float* __restrict__ w,
                          float* __restrict__ out, size_t os)
{
    const float* xr = x + (size_t)blockIdx.x * xs;
    float v[4];
    float s = 0.f, ss = 0.f;
#pragma unroll
    for (int i = 0; i < 4; i++) {
        int c = threadIdx.x + i * 256;
        v[i] = xr[c];
        s  += v[i];
        ss += v[i] * v[i];
    }
    block_reduce2(s, ss);
    float mu  = s * (1.f / 1024.f);
    float var = fmaxf(ss * (1.f / 1024.f) - mu * mu, 0.f);
    float rs  = rsqrtf(var + 1e-5f);
    float* orow = out + (size_t)blockIdx.x * os;
#pragma unroll
    for (int i = 0; i < 4; i++) {
        int c = threadIdx.x + i * 256;
        orow[c] = (v[i] - mu) * rs * w[c];
    }
}

// h[row] += LN(y[row]) * w    (both contiguous [NTOK, 1024])
__global__ void ln_add_kernel(const float* __restrict__ y,
                              const float* __restrict__ w,
                              float* __restrict__ h)
{
    const float* yr = y + (size_t)blockIdx.x * HH;
    float v[4];
    float s = 0.f, ss = 0.f;
#pragma unroll
    for (int i = 0; i < 4; i++) {
        int c = threadIdx.x + i * 256;
        v[i] = yr[c];
        s  += v[i];
        ss += v[i] * v[i];
    }
    block_reduce2(s, ss);
    float mu  = s * (1.f / 1024.f);
    float var = fmaxf(ss * (1.f / 1024.f) - mu * mu, 0.f);
    float rs  = rsqrtf(var + 1e-5f);
    float* hrow = h + (size_t)blockIdx.x * HH;
#pragma unroll
    for (int i = 0; i < 4; i++) {
        int c = threadIdx.x + i * 256;
        hrow[c] += (v[i] - mu) * rs * w[c];
    }
}

// ---------------------------------------------------------------------------
// Depthwise causal conv (K=4) + SiLU.  xn,xc: [B,S,H]; cw: [H,4]; cb: [H]
__global__ void conv_silu_kernel(const float* __restrict__ xn,
                                 const float* __restrict__ cw,
                                 const float* __restrict__ cb,
                                 float* __restrict__ xc)
{
    size_t idx = (size_t)blockIdx.x * blockDim.x + threadIdx.x; // < NTOK*H
    int h = (int)(idx & 1023);
    size_t t = idx >> 10;            // token index b*S+s
    int s = (int)(t % SS);
    float4 wv = *(const float4*)(cw + (size_t)h * 4);
    float w[4] = {wv.x, wv.y, wv.z, wv.w};
    float acc = cb[h];
#pragma unroll
    for (int k = 0; k < 4; k++) {
        int sp = s - 3 + k;
        if (sp >= 0) {
            long off = (long)idx + (long)(k - 3) * HH;
            acc = fmaf(xn[off], w[k], acc);
        }
    }
    // silu
    xc[idx] = acc / (1.f + expf(-acc));
}

// ---------------------------------------------------------------------------
// sLSTM pointwise gate update for step s.
// raw = y_prev @ R (precomputed). Adds Wx[:,s,:] and cell bias, applies gates.
__global__ void gate_step_kernel(const float* __restrict__ raw,
                                 const float* __restrict__ Wx, int s,
                                 const float* __restrict__ cb,
                                 float* __restrict__ y, float* __restrict__ c,
                                 float* __restrict__ n, float* __restrict__ m,
                                 float* __restrict__ yseq)
{
    int idx = blockIdx.x * blockDim.x + threadIdx.x;  // < B*H
    int b = idx >> 10;
    int h = idx & 1023;
    const float* r0 = raw + ((size_t)b << 12);                       // b*4H
    const float* wx = Wx + (((size_t)b * SS + s) << 12) + h;         // [b,s,:]+h

    float ir  = r0[h]        + wx[0]    + cb[h];
    float fr  = r0[h + 1024] + wx[1024] + cb[h + 1024];
    float zr  = r0[h + 2048] + wx[2048] + cb[h + 2048];
    float orr = r0[h + 3072] + wx[3072] + cb[h + 3072];

    // log_sigmoid(fr), numerically stable
    float logsig = (fr >= 0.f) ? -log1pf(expf(-fr)) : (fr - log1pf(expf(fr)));

    float mo = m[idx], no = n[idx], co = c[idx];
    float lfm  = mo + logsig;
    float mnew = (no == 0.f) ? ir : fmaxf(ir, lfm);
    float ig   = expf(ir  - mnew);
    float fg   = expf(lfm - mnew);
    float cnew = fg * co + ig * tanhf(zr);
    float nnew = fg * no + ig;
    float og   = 1.f / (1.f + expf(-orr));
    float ynew = og * cnew / nnew;

    c[idx] = cnew;
    n[idx] = nnew;
    m[idx] = mnew;
    y[idx] = ynew;
    yseq[((size_t)b * SS + s) * HH + h] = ynew;
}

// ---------------------------------------------------------------------------
// Gated FFN activation IN-PLACE: gv[r, u] = gelu_exact(gv[r, u]) * gv[r, U+u]
__global__ void actmul_inplace_kernel(float* __restrict__ gv)
{
    size_t idx = (size_t)blockIdx.x * blockDim.x + threadIdx.x; // < NTOK*U
    size_t r = idx / UU;
    int    u = (int)(idx - r * UU);
    size_t off = r * U2 + u;
    float g = gv[off];
    float v = gv[off + UU];
    float ge = 0.5f * g * (1.f + erff(g * 0.7071067811865476f));
    gv[off] = ge * v;
}

__global__ void zero_kernel(float* __restrict__ p)
{
    size_t idx = (size_t)blockIdx.x * blockDim.x + threadIdx.x;
    p[idx] = 0.f;
}

// ---------------------------------------------------------------------------
extern "C" void kernel_launch(void* const* d_in, const int* in_sizes, int n_in,
                              void* d_out, int out_size)
{
    (void)in_sizes; (void)n_in; (void)out_size;

    const float* x      = (const float*)d_in[0];
    const float* emb_w  = (const float*)d_in[1];
    const float* emb_b  = (const float*)d_in[2];
    const float* conv_w = (const float*)d_in[3];
    const float* conv_b = (const float*)d_in[4];
    const float* Wi     = (const float*)d_in[5];
    const float* Wf     = (const float*)d_in[6];
    const float* Wz     = (const float*)d_in[7];
    const float* Wo     = (const float*)d_in[8];
    const float* R      = (const float*)d_in[9];
    const float* cell_b = (const float*)d_in[10];
    const float* gn_w   = (const float*)d_in[11];
    const float* ln1_w  = (const float*)d_in[12];
    const float* ln2_w  = (const float*)d_in[13];
    const float* ff_up  = (const float*)d_in[14];
    const float* ff_dn  = (const float*)d_in[15];
    const float* post_w = (const float*)d_in[16];
    const float* fc_w   = (const float*)d_in[17];
    const float* fc_b   = (const float*)d_in[18];
    float* out = (float*)d_out;

    float* S_;
    cudaGetSymbolAddress((void**)&S_, g_scratch);
    float* g_h    = S_;
    float* g_xn   = g_h    + (size_t)NTOK * HH;
    float* g_xc   = g_xn   + (size_t)NTOK * HH;   // aliases yseq
    float* g_Wx   = g_xc   + (size_t)NTOK * HH;   // aliases gv
    float* g_raw  = g_Wx   + (size_t)NTOK * H4;
    float* g_st   = g_raw  + (size_t)BB * H4;
    float* g_last = g_st   + (size_t)4 * BB * HH;

    float* g_yseq = g_xc;   // alias
    float* g_gv   = g_Wx;   // alias

    float* g_y = g_st;
    float* g_c = g_st + (size_t)BB * HH;
    float* g_n = g_st + (size_t)2 * BB * HH;
    float* g_m = g_st + (size_t)3 * BB * HH;

    // h = x @ emb_w^T + emb_b   [25600,128] x [1024,128]^T
    gemm_kernel<128,128,16,8,8,true,false,true>
        <<<dim3(HH/128, NTOK/128), 256>>>(x, II, emb_w, II, g_h, HH, emb_b, II);

    for (int l = 0; l < LL; l++) {
        const float* Wg[4] = { Wi + (size_t)l*HH*HH, Wf + (size_t)l*HH*HH,
                               Wz + (size_t)l*HH*HH, Wo + (size_t)l*HH*HH };

        // xn = LN(h)*ln1_w
        ln_kernel<<<NTOK, 256>>>(g_h, HH, ln1_w + (size_t)l*HH, g_xn, HH);
        // xc = silu(causal_conv(xn))
        conv_silu_kernel<<<(NTOK*HH)/256, 256>>>(g_xn,
            conv_w + (size_t)l*HH*KK, conv_b + (size_t)l*HH, g_xc);

        // Wx = [xc@Wi^T | xc@Wf^T | xn@Wz^T | xn@Wo^T]  -> [B,S,4H]
        for (int q = 0; q < 4; q++) {
            const float* Aq = (q < 2) ? g_xc : g_xn;
            gemm_kernel<128,128,16,8,8,true,false,false>
                <<<dim3(HH/128, NTOK/128), 256>>>(Aq, HH, Wg[q], HH,
                                                  g_Wx + (size_t)q*HH, H4,
                                                  nullptr, HH);
        }

        // zero recurrent state (y,c,n,m)
        zero_kernel<<<(4*BB*HH)/256, 256>>>(g_st);

        const float* Rl = R + (size_t)l * HH * H4;   // [H, 4H] row-major (NN)
        const float* cbl = cell_b + (size_t)l * H4;

        for (int s = 0; s < SS; s++) {
            // raw = y_prev @ R    [256,1024] x [1024,4096]
            gemm_kernel<64,128,16,4,8,false,false,false>
                <<<dim3(H4/128, BB/64), 256>>>(g_y, HH, Rl, H4,
                                               g_raw, H4, nullptr, HH);
            gate_step_kernel<<<(BB*HH)/256, 256>>>(g_raw, g_Wx, s, cbl,
                                                   g_y, g_c, g_n, g_m, g_yseq);
        }

        // h += LN(yseq)*gn_w
        ln_add_kernel<<<NTOK, 256>>>(g_yseq, gn_w + (size_t)l*HH, g_h);

        // FFN: fn = LN(h)*ln2_w ; gv = fn @ ff_up^T ; act = gelu(g)*v in-place;
        //      h += act @ ff_dn^T
        ln_kernel<<<NTOK, 256>>>(g_h, HH, ln2_w + (size_t)l*HH, g_xn, HH);
        gemm_kernel<128,128,16,8,8,true,false,false>
            <<<dim3(U2/128, NTOK/128), 256>>>(g_xn, HH,
                                              ff_up + (size_t)l*U2*HH, HH,
                                              g_gv, U2, nullptr, HH);
        actmul_inplace_kernel<<<(NTOK*UU)/256, 256>>>(g_gv);
        gemm_kernel<128,128,16,8,8,true,true,false>
            <<<dim3(HH/128, NTOK/128), 256>>>(g_gv, U2,
                                              ff_dn + (size_t)l*HH*UU, UU,
                                              g_h, HH, nullptr, UU);
    }

    // post-LN only needed for last timestep
    ln_kernel<<<BB, 256>>>(g_h + (size_t)(SS-1)*HH, (size_t)SS*HH,
                           post_w, g_last, HH);
    // out = last @ fc_w^T + fc_b   [256,1024] x [128,1024]^T
    gemm_kernel<64,128,16,4,8,true,false,true>
        <<<dim3(OO/128, BB/64), 256>>>(g_last, HH, fc_w, HH,
                                       out, OO, fc_b, HH);
}

// round 3
// speedup vs baseline: 2.4033x; 2.4033x over previous
#include <cuda_runtime.h>
#include <cuda_bf16.h>
#include <cstddef>
#include <cstdint>

// Problem constants
#define BB   256
#define SS   100
#define II   128
#define HH   1024
#define OO   128
#define LL   2
#define UU   1344
#define KK   4
#define NTOK (BB * SS)          // 25600
#define H4   (4 * HH)           // 4096
#define U2   (2 * UU)           // 2688

// ---------------------------------------------------------------------------
// Scratch layout (floats), with aliasing:
//  h     : NTOK*H
//  xn    : NTOK*H
//  xc    : NTOK*H         (aliases yseq)
//  Wx    : NTOK*4H        (aliases gv; act computed in-place in g half)
//  raw   : B*4H
//  state : 4*B*H          (y,c,n,m)
//  last  : B*H
//  wtf32 : 25,034,752     (tf32-rounded weight copies)
#define W_WI   ((size_t)LL * HH * HH)       // 2,097,152
#define W_R    ((size_t)LL * HH * H4)       // 8,388,608
#define W_UP   ((size_t)LL * U2 * HH)       // 5,505,024
#define W_DN   ((size_t)LL * HH * UU)       // 2,752,512
#define W_TOT  (4 * W_WI + W_R + W_UP + W_DN)
#define SCRATCH_FLOATS (185860096ULL + W_TOT)
__device__ float g_scratch[SCRATCH_FLOATS];

// ---------------------------------------------------------------------------
__device__ __forceinline__ float tf32r(float x)
{
    uint32_t u;
    asm("cvt.rna.tf32.f32 %0, %1;" : "=r"(u) : "f"(x));
    return __uint_as_float(u);
}

__device__ __forceinline__ void cp16(void* s, const void* g)
{
    uint32_t sa = (uint32_t)__cvta_generic_to_shared(s);
    asm volatile("cp.async.cg.shared.global [%0], [%1], 16;\n" :: "r"(sa), "l"(g));
}
__device__ __forceinline__ void cp_commit()
{
    asm volatile("cp.async.commit_group;\n" ::);
}
template<int N>
__device__ __forceinline__ void cp_wait()
{
    asm volatile("cp.async.wait_group %0;\n" :: "n"(N));
}

__device__ __forceinline__ void mma_tf32(float* d, const uint32_t* a, const uint32_t* b)
{
    asm volatile(
        "mma.sync.aligned.m16n8k8.row.col.f32.tf32.tf32.f32 "
        "{%0,%1,%2,%3},{%4,%5,%6,%7},{%8,%9},{%0,%1,%2,%3};"
        : "+f"(d[0]), "+f"(d[1]), "+f"(d[2]), "+f"(d[3])
        : "r"(a[0]), "r"(a[1]), "r"(a[2]), "r"(a[3]),
          "r"(b[0]), "r"(b[1]));
}

// ---------------------------------------------------------------------------
// tf32 tensor-core GEMM.  C[M,N] = A[M,K] * op(B) (+C if ACC)
//   BT=true : B stored [N,K] (NT);  BT=false : B stored [K,N] (NN)
// Tiles: BM=BN=128, BK=16, 256 threads (8 warps, 2x4 of 64x32 warp tiles).
// All operands must already be tf32-rounded. M%128==0, N%128==0, K%16==0.
template<bool BT, bool ACC>
__global__ void __launch_bounds__(256)
gemm_tf32_kernel(const float* __restrict__ A, int lda,
                 const float* __restrict__ B, int ldb,
                 float* __restrict__ C, int ldc, int K)
{
    constexpr int BM = 128, BN = 128, BK = 16;
    constexpr int ASTRIDE = BK + 4;                 // 20 floats (80B, 16B-aligned)
    constexpr int BSTRIDE = BT ? (BK + 4) : (BN + 4); // 20 or 132
    constexpr int BROWS   = BT ? BN : BK;
    constexpr int BRS     = BROWS * BSTRIDE;

    __shared__ __align__(16) float As[2][BM][ASTRIDE];
    __shared__ __align__(16) float Bs[2 * BRS];

    const int tid  = threadIdx.x;
    const int lane = tid & 31;
    const int warp = tid >> 5;
    const int wm = (warp >> 2) * 64;
    const int wn = (warp & 3) * 32;
    const int lr = lane >> 2;   // 0..7
    const int lc = lane & 3;    // 0..3
    const long bm0 = (long)blockIdx.y * BM;
    const long bn0 = (long)blockIdx.x * BN;

    float acc[4][4][4];
#pragma unroll
    for (int mi = 0; mi < 4; mi++)
#pragma unroll
        for (int ni = 0; ni < 4; ni++)
#pragma unroll
            for (int t = 0; t < 4; t++) acc[mi][ni][t] = 0.f;

    auto prefetch = [&](int buf, int k0) {
        // A: 128x16 floats = 512 16B chunks
#pragma unroll
        for (int j = 0; j < 2; j++) {
            int i = tid + j * 256;
            int row = i >> 2, kp = (i & 3) * 4;
            cp16(&As[buf][row][kp], A + (bm0 + row) * (long)lda + k0 + kp);
        }
        if (BT) {
#pragma unroll
            for (int j = 0; j < 2; j++) {
                int i = tid + j * 256;
                int row = i >> 2, kp = (i & 3) * 4;
                cp16(&Bs[buf * BRS + row * BSTRIDE + kp],
                     B + (bn0 + row) * (long)ldb + k0 + kp);
            }
        } else {
#pragma unroll
            for (int j = 0; j < 2; j++) {
                int i = tid + j * 256;
                int krow = i >> 5, np = (i & 31) * 4;
                cp16(&Bs[buf * BRS + krow * BSTRIDE + np],
                     B + (long)(k0 + krow) * ldb + bn0 + np);
            }
        }
    };

    auto compute = [&](int buf) {
#pragma unroll
        for (int kk = 0; kk < BK; kk += 8) {
            uint32_t a[4][4], b[4][2];
#pragma unroll
            for (int mi = 0; mi < 4; mi++) {
                int m0 = wm + mi * 16;
                a[mi][0] = __float_as_uint(As[buf][m0 + lr][kk + lc]);
                a[mi][1] = __float_as_uint(As[buf][m0 + 8 + lr][kk + lc]);
                a[mi][2] = __float_as_uint(As[buf][m0 + lr][kk + 4 + lc]);
                a[mi][3] = __float_as_uint(As[buf][m0 + 8 + lr][kk + 4 + lc]);
            }
#pragma unroll
            for (int ni = 0; ni < 4; ni++) {
                int n0 = wn + ni * 8;
                if (BT) {
                    b[ni][0] = __float_as_uint(Bs[buf * BRS + (n0 + lr) * BSTRIDE + kk + lc]);
                    b[ni][1] = __float_as_uint(Bs[buf * BRS + (n0 + lr) * BSTRIDE + kk + 4 + lc]);
                } else {
                    b[ni][0] = __float_as_uint(Bs[buf * BRS + (kk + lc) * BSTRIDE + n0 + lr]);
                    b[ni][1] = __float_as_uint(Bs[buf * BRS + (kk + 4 + lc) * BSTRIDE + n0 + lr]);
                }
            }
#pragma unroll
            for (int mi = 0; mi < 4; mi++)
#pragma unroll
                for (int ni = 0; ni < 4; ni++)
                    mma_tf32(acc[mi][ni], a[mi], b[ni]);
        }
    };

    const int NIT = K / BK;
    prefetch(0, 0);
    cp_commit();
    for (int it = 0; it < NIT; ++it) {
        if (it + 1 < NIT) {
            prefetch((it + 1) & 1, (it + 1) * BK);
            cp_commit();
            cp_wait<1>();
        } else {
            cp_wait<0>();
        }
        __syncthreads();
        compute(it & 1);
        __syncthreads();
    }

    // Epilogue
#pragma unroll
    for (int mi = 0; mi < 4; mi++) {
        long r0 = bm0 + wm + mi * 16 + lr;
#pragma unroll
        for (int ni = 0; ni < 4; ni++) {
            long c0 = bn0 + wn + ni * 8 + lc * 2;
            float2* p0 = (float2*)(C + r0 * (long)ldc + c0);
            float2* p1 = (float2*)(C + (r0 + 8) * (long)ldc + c0);
            if (ACC) {
                float2 v0 = *p0, v1 = *p1;
                v0.x += acc[mi][ni][0]; v0.y += acc[mi][ni][1];
                v1.x += acc[mi][ni][2]; v1.y += acc[mi][ni][3];
                *p0 = v0; *p1 = v1;
            } else {
                *p0 = make_float2(acc[mi][ni][0], acc[mi][ni][1]);
                *p1 = make_float2(acc[mi][ni][2], acc[mi][ni][3]);
            }
        }
    }
}

// ---------------------------------------------------------------------------
// fp32 SIMT GEMM (kept for the small emb / fc GEMMs).
template<int BM, int BN, int BK, int TM, int TN, bool BT, bool ACC, bool BIAS>
__global__ void __launch_bounds__(256)
gemm_kernel(const float* __restrict__ A, int lda,
            const float* __restrict__ B, int ldb,
            float* __restrict__ C, int ldc,
            const float* __restrict__ bias,
            int K)
{
    constexpr int TX = BN / TN;
    constexpr int TY = BM / TM;
    constexpr int NT = TX * TY;

    __shared__ float As[BK][BM + 4];
    __shared__ float Bs[BK][BN + 4];

    const int tid = threadIdx.x;
    const int tx = tid % TX;
    const int ty = tid / TX;
    const long bm0 = (long)blockIdx.y * BM;
    const long bn0 = (long)blockIdx.x * BN;

    float acc[TM][TN];
#pragma unroll
    for (int i = 0; i < TM; i++)
#pragma unroll
        for (int j = 0; j < TN; j++) acc[i][j] = 0.f;

    for (int k0 = 0; k0 < K; k0 += BK) {
#pragma unroll
        for (int i = tid * 4; i < BM * BK; i += NT * 4) {
            int r  = i / BK;
            int kk = i % BK;
            float4 v = *(const float4*)(A + (bm0 + r) * (long)lda + (k0 + kk));
            As[kk + 0][r] = v.x;
            As[kk + 1][r] = v.y;
            As[kk + 2][r] = v.z;
            As[kk + 3][r] = v.w;
        }
        if (BT) {
#pragma unroll
            for (int i = tid * 4; i < BN * BK; i += NT * 4) {
                int r  = i / BK;
                int kk = i % BK;
                float4 v = *(const float4*)(B + (bn0 + r) * (long)ldb + (k0 + kk));
                Bs[kk + 0][r] = v.x;
                Bs[kk + 1][r] = v.y;
                Bs[kk + 2][r] = v.z;
                Bs[kk + 3][r] = v.w;
            }
        } else {
#pragma unroll
            for (int i = tid * 4; i < BK * BN; i += NT * 4) {
                int kk = i / BN;
                int c  = i % BN;
                float4 v = *(const float4*)(B + (long)(k0 + kk) * ldb + bn0 + c);
                *(float4*)&Bs[kk][c] = v;
            }
        }
        __syncthreads();

#pragma unroll
        for (int kk = 0; kk < BK; kk++) {
            float a[TM], b[TN];
#pragma unroll
            for (int i = 0; i < TM; i += 4)
                *(float4*)&a[i] = *(const float4*)&As[kk][ty * TM + i];
#pragma unroll
            for (int j = 0; j < TN; j += 4)
                *(float4*)&b[j] = *(const float4*)&Bs[kk][tx * TN + j];
#pragma unroll
            for (int i = 0; i < TM; i++)
#pragma unroll
                for (int j = 0; j < TN; j++)
                    acc[i][j] = fmaf(a[i], b[j], acc[i][j]);
        }
        __syncthreads();
    }

#pragma unroll
    for (int i = 0; i < TM; i++) {
        long row = bm0 + ty * TM + i;
#pragma unroll
        for (int j = 0; j < TN; j++) {
            long col = bn0 + tx * TN + j;
            float v = acc[i][j];
            if (BIAS) v += bias[col];
            long off = row * (long)ldc + col;
            if (ACC) v += C[off];
            C[off] = v;
        }
    }
}

// ---------------------------------------------------------------------------
__device__ __forceinline__ void block_reduce2(float& s, float& ss)
{
    __shared__ float sh[16];
    int lane = threadIdx.x & 31;
    int wid  = threadIdx.x >> 5;
#pragma unroll
    for (int o = 16; o > 0; o >>= 1) {
        s  += __shfl_xor_sync(0xFFFFFFFFu, s,  o);
        ss += __shfl_xor_sync(0xFFFFFFFFu, ss, o);
    }
    if (lane == 0) { sh[wid] = s; sh[8 + wid] = ss; }
    __syncthreads();
    if (threadIdx.x < 32) {
        float a = (lane < 8) ? sh[lane]     : 0.f;
        float b = (lane < 8) ? sh[8 + lane] : 0.f;
#pragma unroll
        for (int o = 4; o > 0; o >>= 1) {
            a += __shfl_xor_sync(0xFFFFFFFFu, a, o);
            b += __shfl_xor_sync(0xFFFFFFFFu, b, o);
        }
        if (lane == 0) { sh[0] = a; sh[8] = b; }
    }
    __syncthreads();
    s  = sh[0];
    ss = sh[8];
}

// out[row] = LN(x[row]) * w, optionally tf32-rounded for tensor-core consumers
template<bool ROUND>
__global__ void ln_kernel(const float* __restrict__ x, size_t xs,
                          const float* __restrict__ w,
                          float* __restrict__ out, size_t os)
{
    const float* xr = x + (size_t)blockIdx.x * xs;
    float v[4];
    float s = 0.f, ss = 0.f;
#pragma unroll
    for (int i = 0; i < 4; i++) {
        int c = threadIdx.x + i * 256;
        v[i] = xr[c];
        s  += v[i];
        ss += v[i] * v[i];
    }
    block_reduce2(s, ss);
    float mu  = s * (1.f / 1024.f);
    float var = fmaxf(ss * (1.f / 1024.f) - mu * mu, 0.f);
    float rs  = rsqrtf(var + 1e-5f);
    float* orow = out + (size_t)blockIdx.x * os;
#pragma unroll
    for (int i = 0; i < 4; i++) {
        int c = threadIdx.x + i * 256;
        float o = (v[i] - mu) * rs * w[c];
        orow[c] = ROUND ? tf32r(o) : o;
    }
}

// h[row] += LN(y[row]) * w
__global__ void ln_add_kernel(const float* __restrict__ y,
                              const float* __restrict__ w,
                              float* __restrict__ h)
{
    const float* yr = y + (size_t)blockIdx.x * HH;
    float v[4];
    float s = 0.f, ss = 0.f;
#pragma unroll
    for (int i = 0; i < 4; i++) {
        int c = threadIdx.x + i * 256;
        v[i] = yr[c];
        s  += v[i];
        ss += v[i] * v[i];
    }
    block_reduce2(s, ss);
    float mu  = s * (1.f / 1024.f);
    float var = fmaxf(ss * (1.f / 1024.f) - mu * mu, 0.f);
    float rs  = rsqrtf(var + 1e-5f);
    float* hrow = h + (size_t)blockIdx.x * HH;
#pragma unroll
    for (int i = 0; i < 4; i++) {
        int c = threadIdx.x + i * 256;
        hrow[c] += (v[i] - mu) * rs * w[c];
    }
}

// ---------------------------------------------------------------------------
// Depthwise causal conv (K=4) + SiLU, output tf32-rounded.
__global__ void conv_silu_kernel(const float* __restrict__ xn,
                                 const float* __restrict__ cw,
                                 const float* __restrict__ cb,
                                 float* __restrict__ xc)
{
    size_t idx = (size_t)blockIdx.x * blockDim.x + threadIdx.x; // < NTOK*H
    int h = (int)(idx & 1023);
    size_t t = idx >> 10;
    int s = (int)(t % SS);
    float4 wv = *(const float4*)(cw + (size_t)h * 4);
    float w[4] = {wv.x, wv.y, wv.z, wv.w};
    float acc = cb[h];
#pragma unroll
    for (int k = 0; k < 4; k++) {
        int sp = s - 3 + k;
        if (sp >= 0) {
            long off = (long)idx + (long)(k - 3) * HH;
            acc = fmaf(xn[off], w[k], acc);
        }
    }
    xc[idx] = tf32r(acc / (1.f + expf(-acc)));
}

// ---------------------------------------------------------------------------
// sLSTM gate update for step s. y stored tf32-rounded (GEMM input),
// yseq stored full fp32 (residual/LN path).
__global__ void gate_step_kernel(const float* __restrict__ raw,
                                 const float* __restrict__ Wx, int s,
                                 const float* __restrict__ cb,
                                 float* __restrict__ y, float* __restrict__ c,
                                 float* __restrict__ n, float* __restrict__ m,
                                 float* __restrict__ yseq)
{
    int idx = blockIdx.x * blockDim.x + threadIdx.x;  // < B*H
    int b = idx >> 10;
    int h = idx & 1023;
    const float* r0 = raw + ((size_t)b << 12);
    const float* wx = Wx + (((size_t)b * SS + s) << 12) + h;

    float ir  = r0[h]        + wx[0]    + cb[h];
    float fr  = r0[h + 1024] + wx[1024] + cb[h + 1024];
    float zr  = r0[h + 2048] + wx[2048] + cb[h + 2048];
    float orr = r0[h + 3072] + wx[3072] + cb[h + 3072];

    float logsig = (fr >= 0.f) ? -log1pf(expf(-fr)) : (fr - log1pf(expf(fr)));

    float mo = m[idx], no = n[idx], co = c[idx];
    float lfm  = mo + logsig;
    float mnew = (no == 0.f) ? ir : fmaxf(ir, lfm);
    float ig   = expf(ir  - mnew);
    float fg   = expf(lfm - mnew);
    float cnew = fg * co + ig * tanhf(zr);
    float nnew = fg * no + ig;
    float og   = 1.f / (1.f + expf(-orr));
    float ynew = og * cnew / nnew;

    c[idx] = cnew;
    n[idx] = nnew;
    m[idx] = mnew;
    y[idx] = tf32r(ynew);
    yseq[((size_t)b * SS + s) * HH + h] = ynew;
}

// ---------------------------------------------------------------------------
// Gated FFN activation IN-PLACE, output tf32-rounded.
__global__ void actmul_inplace_kernel(float* __restrict__ gv)
{
    size_t idx = (size_t)blockIdx.x * blockDim.x + threadIdx.x; // < NTOK*U
    size_t r = idx / UU;
    int    u = (int)(idx - r * UU);
    size_t off = r * U2 + u;
    float g = gv[off];
    float v = gv[off + UU];
    float ge = 0.5f * g * (1.f + erff(g * 0.7071067811865476f));
    gv[off] = tf32r(ge * v);
}

__global__ void zero_kernel(float* __restrict__ p)
{
    size_t idx = (size_t)blockIdx.x * blockDim.x + threadIdx.x;
    p[idx] = 0.f;
}

// tf32-round a weight tensor into scratch.
__global__ void round_tf32_kernel(const float* __restrict__ src,
                                  float* __restrict__ dst, size_t nelem)
{
    size_t idx = (size_t)blockIdx.x * blockDim.x + threadIdx.x;
    if (idx < nelem) dst[idx] = tf32r(src[idx]);
}

// ---------------------------------------------------------------------------
extern "C" void kernel_launch(void* const* d_in, const int* in_sizes, int n_in,
                              void* d_out, int out_size)
{
    (void)in_sizes; (void)n_in; (void)out_size;

    const float* x      = (const float*)d_in[0];
    const float* emb_w  = (const float*)d_in[1];
    const float* emb_b  = (const float*)d_in[2];
    const float* conv_w = (const float*)d_in[3];
    const float* conv_b = (const float*)d_in[4];
    const float* Wi     = (const float*)d_in[5];
    const float* Wf     = (const float*)d_in[6];
    const float* Wz     = (const float*)d_in[7];
    const float* Wo     = (const float*)d_in[8];
    const float* R      = (const float*)d_in[9];
    const float* cell_b = (const float*)d_in[10];
    const float* gn_w   = (const float*)d_in[11];
    const float* ln1_w  = (const float*)d_in[12];
    const float* ln2_w  = (const float*)d_in[13];
    const float* ff_up  = (const float*)d_in[14];
    const float* ff_dn  = (const float*)d_in[15];
    const float* post_w = (const float*)d_in[16];
    const float* fc_w   = (const float*)d_in[17];
    const float* fc_b   = (const float*)d_in[18];
    float* out = (float*)d_out;

    float* S_;
    cudaGetSymbolAddress((void**)&S_, g_scratch);
    float* g_h    = S_;
    float* g_xn   = g_h    + (size_t)NTOK * HH;
    float* g_xc   = g_xn   + (size_t)NTOK * HH;   // aliases yseq
    float* g_Wx   = g_xc   + (size_t)NTOK * HH;   // aliases gv
    float* g_raw  = g_Wx   + (size_t)NTOK * H4;
    float* g_st   = g_raw  + (size_t)BB * H4;
    float* g_last = g_st   + (size_t)4 * BB * HH;
    float* g_w    = g_last + (size_t)BB * HH;

    float* w_i  = g_w;
    float* w_f  = w_i  + W_WI;
    float* w_z  = w_f  + W_WI;
    float* w_o  = w_z  + W_WI;
    float* w_r  = w_o  + W_WI;
    float* w_up = w_r  + W_R;
    float* w_dn = w_up + W_UP;

    float* g_yseq = g_xc;   // alias
    float* g_gv   = g_Wx;   // alias

    float* g_y = g_st;
    float* g_c = g_st + (size_t)BB * HH;
    float* g_n = g_st + (size_t)2 * BB * HH;
    float* g_m = g_st + (size_t)3 * BB * HH;

    // tf32-round weight copies
    round_tf32_kernel<<<(unsigned)((W_WI + 255) / 256), 256>>>(Wi,    w_i,  W_WI);
    round_tf32_kernel<<<(unsigned)((W_WI + 255) / 256), 256>>>(Wf,    w_f,  W_WI);
    round_tf32_kernel<<<(unsigned)((W_WI + 255) / 256), 256>>>(Wz,    w_z,  W_WI);
    round_tf32_kernel<<<(unsigned)((W_WI + 255) / 256), 256>>>(Wo,    w_o,  W_WI);
    round_tf32_kernel<<<(unsigned)((W_R  + 255) / 256), 256>>>(R,     w_r,  W_R);
    round_tf32_kernel<<<(unsigned)((W_UP + 255) / 256), 256>>>(ff_up, w_up, W_UP);
    round_tf32_kernel<<<(unsigned)((W_DN + 255) / 256), 256>>>(ff_dn, w_dn, W_DN);

    // h = x @ emb_w^T + emb_b  (small K=128; fp32 SIMT)
    gemm_kernel<128,128,16,8,8,true,false,true>
        <<<dim3(HH/128, NTOK/128), 256>>>(x, II, emb_w, II, g_h, HH, emb_b, II);

    for (int l = 0; l < LL; l++) {
        const float* Wg[4] = { w_i + (size_t)l*HH*HH, w_f + (size_t)l*HH*HH,
                               w_z + (size_t)l*HH*HH, w_o + (size_t)l*HH*HH };

        // xn = LN(h)*ln1_w  (tf32-rounded; also conv input)
        ln_kernel<true><<<NTOK, 256>>>(g_h, HH, ln1_w + (size_t)l*HH, g_xn, HH);
        // xc = silu(causal_conv(xn))  (tf32-rounded)
        conv_silu_kernel<<<(NTOK*HH)/256, 256>>>(g_xn,
            conv_w + (size_t)l*HH*KK, conv_b + (size_t)l*HH, g_xc);

        // Wx = [xc@Wi^T | xc@Wf^T | xn@Wz^T | xn@Wo^T]  -> [B,S,4H]
        for (int q = 0; q < 4; q++) {
            const float* Aq = (q < 2) ? g_xc : g_xn;
            gemm_tf32_kernel<true,false>
                <<<dim3(HH/128, NTOK/128), 256>>>(Aq, HH, Wg[q], HH,
                                                  g_Wx + (size_t)q*HH, H4, HH);
        }

        // zero recurrent state (y,c,n,m)
        zero_kernel<<<(4*BB*HH)/256, 256>>>(g_st);

        const float* Rl  = w_r + (size_t)l * HH * H4;   // [H,4H] (NN)
        const float* cbl = cell_b + (size_t)l * H4;

        for (int s = 0; s < SS; s++) {
            // raw = y_prev @ R    [256,1024] x [1024,4096]
            gemm_tf32_kernel<false,false>
                <<<dim3(H4/128, BB/128), 256>>>(g_y, HH, Rl, H4,
                                                g_raw, H4, HH);
            gate_step_kernel<<<(BB*HH)/256, 256>>>(g_raw, g_Wx, s, cbl,
                                                   g_y, g_c, g_n, g_m, g_yseq);
        }

        // h += LN(yseq)*gn_w
        ln_add_kernel<<<NTOK, 256>>>(g_yseq, gn_w + (size_t)l*HH, g_h);

        // FFN
        ln_kernel<true><<<NTOK, 256>>>(g_h, HH, ln2_w + (size_t)l*HH, g_xn, HH);
        gemm_tf32_kernel<true,false>
            <<<dim3(U2/128, NTOK/128), 256>>>(g_xn, HH,
                                              w_up + (size_t)l*U2*HH, HH,
                                              g_gv, U2, HH);
        actmul_inplace_kernel<<<(NTOK*UU)/256, 256>>>(g_gv);
        gemm_tf32_kernel<true,true>
            <<<dim3(HH/128, NTOK/128), 256>>>(g_gv, U2,
                                              w_dn + (size_t)l*HH*UU, UU,
                                              g_h, HH, UU);
    }

    // post-LN only needed for last timestep
    ln_kernel<false><<<BB, 256>>>(g_h + (size_t)(SS-1)*HH, (size_t)SS*HH,
                                  post_w, g_last, HH);
    // out = last @ fc_w^T + fc_b
    gemm_kernel<64,128,16,4,8,true,false,true>
        <<<dim3(OO/128, BB/64), 256>>>(g_last, HH, fc_w, HH,
                                       out, OO, fc_b, HH);
}

// round 4
// speedup vs baseline: 2.9062x; 1.2093x over previous
#include <cuda_runtime.h>
#include <cuda_bf16.h>
#include <cstddef>
#include <cstdint>

// Problem constants
#define BB   256
#define SS   100
#define II   128
#define HH   1024
#define OO   128
#define LL   2
#define UU   1344
#define KK   4
#define NTOK (BB * SS)          // 25600
#define H4   (4 * HH)           // 4096
#define U2   (2 * UU)           // 2688

// ---------------------------------------------------------------------------
// Scratch layout (floats), with aliasing:
//  h     : NTOK*H
//  xn    : NTOK*H
//  xc    : NTOK*H         (aliases yseq)
//  Wx    : NTOK*4H        (aliases gv; act computed in-place in g half)
//  raw   : B*4H           (reused as ybuf0/ybuf1 for persistent scan)
//  state : 4*B*H          (unused now; kept for layout stability)
//  last  : B*H
//  weights (tf32-rounded, reorganized):
//    w_if : LL*2*HH*HH = 4,194,304   ([l][Wi;Wf] stacked)
//    w_zo : LL*2*HH*HH = 4,194,304   ([l][Wz;Wo] stacked)
//    w_r  : LL*HH*H4   = 8,388,608
//    w_up : LL*U2*HH   = 5,505,024
//    w_dn : LL*HH*UU   = 2,752,512
#define W_IFS  ((size_t)LL * 2 * HH * HH)   // 4,194,304
#define W_R    ((size_t)LL * HH * H4)       // 8,388,608
#define W_UP   ((size_t)LL * U2 * HH)       // 5,505,024
#define W_DN   ((size_t)LL * HH * UU)       // 2,752,512
#define W_TOT  (2 * W_IFS + W_R + W_UP + W_DN)
#define SCRATCH_FLOATS (185860096ULL + W_TOT)
__device__ float g_scratch[SCRATCH_FLOATS];

// grid barrier state for persistent scan kernel
__device__ unsigned g_bar_cnt = 0;
__device__ unsigned g_bar_phase = 0;

// ---------------------------------------------------------------------------
__device__ __forceinline__ float tf32r(float x)
{
    uint32_t u;
    asm("cvt.rna.tf32.f32 %0, %1;" : "=r"(u) : "f"(x));
    return __uint_as_float(u);
}

__device__ __forceinline__ void cp16(void* s, const void* g)
{
    uint32_t sa = (uint32_t)__cvta_generic_to_shared(s);
    asm volatile("cp.async.cg.shared.global [%0], [%1], 16;\n" :: "r"(sa), "l"(g));
}
__device__ __forceinline__ void cp_commit()
{
    asm volatile("cp.async.commit_group;\n" ::);
}
template<int N>
__device__ __forceinline__ void cp_wait()
{
    asm volatile("cp.async.wait_group %0;\n" :: "n"(N));
}

__device__ __forceinline__ void mma_tf32(float* d, const uint32_t* a, const uint32_t* b)
{
    asm volatile(
        "mma.sync.aligned.m16n8k8.row.col.f32.tf32.tf32.f32 "
        "{%0,%1,%2,%3},{%4,%5,%6,%7},{%8,%9},{%0,%1,%2,%3};"
        : "+f"(d[0]), "+f"(d[1]), "+f"(d[2]), "+f"(d[3])
        : "r"(a[0]), "r"(a[1]), "r"(a[2]), "r"(a[3]),
          "r"(b[0]), "r"(b[1]));
}

// ---------------------------------------------------------------------------
// tf32 tensor-core GEMM (parallel GEMMs).  C[M,N] = A[M,K] * B^T (+C if ACC)
// B stored [N,K]. Tiles 128x128x16, 256 threads.
template<bool ACC>
__global__ void __launch_bounds__(256)
gemm_tf32_kernel(const float* __restrict__ A, int lda,
                 const float* __restrict__ B, int ldb,
                 float* __restrict__ C, int ldc, int K)
{
    constexpr int BM = 128, BK = 16;
    constexpr int ASTRIDE = BK + 4;
    constexpr int BSTRIDE = BK + 4;
    constexpr int BRS = 128 * BSTRIDE;

    __shared__ __align__(16) float As[2][BM][ASTRIDE];
    __shared__ __align__(16) float Bs[2 * BRS];

    const int tid  = threadIdx.x;
    const int lane = tid & 31;
    const int warp = tid >> 5;
    const int wm = (warp >> 2) * 64;
    const int wn = (warp & 3) * 32;
    const int lr = lane >> 2;
    const int lc = lane & 3;
    const long bm0 = (long)blockIdx.y * BM;
    const long bn0 = (long)blockIdx.x * 128;

    float acc[4][4][4];
#pragma unroll
    for (int mi = 0; mi < 4; mi++)
#pragma unroll
        for (int ni = 0; ni < 4; ni++)
#pragma unroll
            for (int t = 0; t < 4; t++) acc[mi][ni][t] = 0.f;

    auto prefetch = [&](int buf, int k0) {
#pragma unroll
        for (int j = 0; j < 2; j++) {
            int i = tid + j * 256;
            int row = i >> 2, kp = (i & 3) * 4;
            cp16(&As[buf][row][kp], A + (bm0 + row) * (long)lda + k0 + kp);
        }
#pragma unroll
        for (int j = 0; j < 2; j++) {
            int i = tid + j * 256;
            int row = i >> 2, kp = (i & 3) * 4;
            cp16(&Bs[buf * BRS + row * BSTRIDE + kp],
                 B + (bn0 + row) * (long)ldb + k0 + kp);
        }
    };

    auto compute = [&](int buf) {
#pragma unroll
        for (int kk = 0; kk < BK; kk += 8) {
            uint32_t a[4][4], b[4][2];
#pragma unroll
            for (int mi = 0; mi < 4; mi++) {
                int m0 = wm + mi * 16;
                a[mi][0] = __float_as_uint(As[buf][m0 + lr][kk + lc]);
                a[mi][1] = __float_as_uint(As[buf][m0 + 8 + lr][kk + lc]);
                a[mi][2] = __float_as_uint(As[buf][m0 + lr][kk + 4 + lc]);
                a[mi][3] = __float_as_uint(As[buf][m0 + 8 + lr][kk + 4 + lc]);
            }
#pragma unroll
            for (int ni = 0; ni < 4; ni++) {
                int n0 = wn + ni * 8;
                b[ni][0] = __float_as_uint(Bs[buf * BRS + (n0 + lr) * BSTRIDE + kk + lc]);
                b[ni][1] = __float_as_uint(Bs[buf * BRS + (n0 + lr) * BSTRIDE + kk + 4 + lc]);
            }
#pragma unroll
            for (int mi = 0; mi < 4; mi++)
#pragma unroll
                for (int ni = 0; ni < 4; ni++)
                    mma_tf32(acc[mi][ni], a[mi], b[ni]);
        }
    };

    const int NIT = K / BK;
    prefetch(0, 0);
    cp_commit();
    for (int it = 0; it < NIT; ++it) {
        if (it + 1 < NIT) {
            prefetch((it + 1) & 1, (it + 1) * BK);
            cp_commit();
            cp_wait<1>();
        } else {
            cp_wait<0>();
        }
        __syncthreads();
        compute(it & 1);
        __syncthreads();
    }

#pragma unroll
    for (int mi = 0; mi < 4; mi++) {
        long r0 = bm0 + wm + mi * 16 + lr;
#pragma unroll
        for (int ni = 0; ni < 4; ni++) {
            long c0 = bn0 + wn + ni * 8 + lc * 2;
            float2* p0 = (float2*)(C + r0 * (long)ldc + c0);
            float2* p1 = (float2*)(C + (r0 + 8) * (long)ldc + c0);
            if (ACC) {
                float2 v0 = *p0, v1 = *p1;
                v0.x += acc[mi][ni][0]; v0.y += acc[mi][ni][1];
                v1.x += acc[mi][ni][2]; v1.y += acc[mi][ni][3];
                *p0 = v0; *p1 = v1;
            } else {
                *p0 = make_float2(acc[mi][ni][0], acc[mi][ni][1]);
                *p1 = make_float2(acc[mi][ni][2], acc[mi][ni][3]);
            }
        }
    }
}

// ---------------------------------------------------------------------------
// Persistent fused sLSTM scan kernel. One launch runs all SS steps.
// Grid: exactly 128 CTAs x 256 threads. CTA = (mt = bid>>5 in [0,4),
// ht = bid&31 in [0,32)). Output tile: 64 batch rows x (4 gates x 32 h).
// State (c,n,m) lives in registers. y double-buffered in global scratch.
#define SC_CTAS 128

__device__ __forceinline__ void grid_bar()
{
    __syncthreads();
    __threadfence();
    if (threadIdx.x == 0) {
        unsigned p = *((volatile unsigned*)&g_bar_phase);
        unsigned my = atomicAdd(&g_bar_cnt, 1u);
        if (my == SC_CTAS - 1) {
            g_bar_cnt = 0;
            __threadfence();
            atomicAdd(&g_bar_phase, 1u);
        } else {
            while (*((volatile unsigned*)&g_bar_phase) == p) { }
        }
    }
    __syncthreads();
    __threadfence();
}

__global__ void __launch_bounds__(256)
scan_kernel(const float* __restrict__ Wx, const float* __restrict__ Rw,
            const float* __restrict__ cb,
            float* __restrict__ yb0, float* __restrict__ yb1,
            float* __restrict__ yseq)
{
    extern __shared__ float sm[];
    constexpr int ASTR = 36, BSTR = 132, BK = 32, RSTR = 132;
    float* As   = sm;                    // [2][64][36]  = 4608 floats
    float* Bs   = sm + 2 * 64 * ASTR;    // [2][32][132] = 8448 floats
    float* rawS = sm;                    // [64][132]    = 8448 floats (aliases)

    const int tid  = threadIdx.x;
    const int lane = tid & 31;
    const int warp = tid >> 5;
    const int wm = (warp >> 2) * 32;     // 2 warp rows x 32
    const int wn = (warp & 3) * 32;      // 4 warp cols x 32
    const int lr = lane >> 2;
    const int lc = lane & 3;
    const int mt = blockIdx.x >> 5;      // 0..3
    const int ht = blockIdx.x & 31;      // 0..31

    // gate-update assignment: thread owns h = ht*32 + (tid&31),
    // rows (tid>>5)*8 .. +7 within its 64-row block.
    const int hl = tid & 31;
    const int rg = tid >> 5;
    const int h  = ht * 32 + hl;
    const long acol = (long)mt * 64;     // batch-row offset

    float cbv[4];
#pragma unroll
    for (int g = 0; g < 4; g++) cbv[g] = cb[g * 1024 + h];

    float stc[8], stn[8], stm[8];
#pragma unroll
    for (int j = 0; j < 8; j++) { stc[j] = 0.f; stn[j] = 0.f; stm[j] = 0.f; }

    // zero initial y buffer (yb0)
    {
        float4 z = make_float4(0.f, 0.f, 0.f, 0.f);
        float* p = yb0 + (size_t)blockIdx.x * 2048 + tid * 8;
        *(float4*)p = z;
        *(float4*)(p + 4) = z;
    }
    grid_bar();

    for (int s = 0; s < SS; s++) {
        const float* ycur = (s & 1) ? yb1 : yb0;
        float*       ynxt = (s & 1) ? yb0 : yb1;

        float acc[2][4][4];
#pragma unroll
        for (int mi = 0; mi < 2; mi++)
#pragma unroll
            for (int ni = 0; ni < 4; ni++)
#pragma unroll
                for (int t = 0; t < 4; t++) acc[mi][ni][t] = 0.f;

        auto prefetch = [&](int buf, int k0) {
            // A: 64 x 32 floats = 512 cp16 (2/thread)
#pragma unroll
            for (int j = 0; j < 2; j++) {
                int i = tid + j * 256;
                int row = i >> 3, kp = (i & 7) * 4;
                cp16(&As[(buf * 64 + row) * ASTR + kp],
                     ycur + (acol + row) * 1024 + k0 + kp);
            }
            // B: 32 x 128 floats = 1024 cp16 (4/thread), gathered gate cols
#pragma unroll
            for (int j = 0; j < 4; j++) {
                int i = tid + j * 256;
                int kr = i >> 5, c4 = (i & 31) * 4;
                int g = c4 >> 5, u = c4 & 31;
                cp16(&Bs[(buf * 32 + kr) * BSTR + c4],
                     Rw + (long)(k0 + kr) * 4096 + g * 1024 + ht * 32 + u);
            }
        };

        auto compute = [&](int buf) {
#pragma unroll
            for (int kk = 0; kk < BK; kk += 8) {
                uint32_t a[2][4], b[4][2];
#pragma unroll
                for (int mi = 0; mi < 2; mi++) {
                    int m0 = wm + mi * 16;
                    a[mi][0] = __float_as_uint(As[(buf * 64 + m0 + lr) * ASTR + kk + lc]);
                    a[mi][1] = __float_as_uint(As[(buf * 64 + m0 + 8 + lr) * ASTR + kk + lc]);
                    a[mi][2] = __float_as_uint(As[(buf * 64 + m0 + lr) * ASTR + kk + 4 + lc]);
                    a[mi][3] = __float_as_uint(As[(buf * 64 + m0 + 8 + lr) * ASTR + kk + 4 + lc]);
                }
#pragma unroll
                for (int ni = 0; ni < 4; ni++) {
                    int n0 = wn + ni * 8;
                    b[ni][0] = __float_as_uint(Bs[(buf * 32 + kk + lc) * BSTR + n0 + lr]);
                    b[ni][1] = __float_as_uint(Bs[(buf * 32 + kk + 4 + lc) * BSTR + n0 + lr]);
                }
#pragma unroll
                for (int mi = 0; mi < 2; mi++)
#pragma unroll
                    for (int ni = 0; ni < 4; ni++)
                        mma_tf32(acc[mi][ni], a[mi], b[ni]);
            }
        };

        constexpr int NIT = 1024 / BK;   // 32
        prefetch(0, 0);
        cp_commit();
        for (int it = 0; it < NIT; ++it) {
            if (it + 1 < NIT) {
                prefetch((it + 1) & 1, (it + 1) * BK);
                cp_commit();
                cp_wait<1>();
            } else {
                cp_wait<0>();
            }
            __syncthreads();
            compute(it & 1);
            __syncthreads();
        }

        // stage raw tile to smem (aliases As/Bs; GEMM done)
#pragma unroll
        for (int mi = 0; mi < 2; mi++) {
            int r0 = wm + mi * 16 + lr;
#pragma unroll
            for (int ni = 0; ni < 4; ni++) {
                int c0 = wn + ni * 8 + lc * 2;
                *(float2*)&rawS[r0 * RSTR + c0] =
                    make_float2(acc[mi][ni][0], acc[mi][ni][1]);
                *(float2*)&rawS[(r0 + 8) * RSTR + c0] =
                    make_float2(acc[mi][ni][2], acc[mi][ni][3]);
            }
        }
        __syncthreads();

        // fused gate update: 8 (b,h) pairs per thread, state in registers
#pragma unroll
        for (int j = 0; j < 8; j++) {
            int row = rg * 8 + j;
            long bb = acol + row;
            const float* wx = Wx + ((bb * SS + s) << 12) + h;

            float ir  = rawS[row * RSTR + hl]      + wx[0]    + cbv[0];
            float fr  = rawS[row * RSTR + 32 + hl] + wx[1024] + cbv[1];
            float zr  = rawS[row * RSTR + 64 + hl] + wx[2048] + cbv[2];
            float orr = rawS[row * RSTR + 96 + hl] + wx[3072] + cbv[3];

            float logsig = (fr >= 0.f) ? -log1pf(expf(-fr))
                                       : (fr - log1pf(expf(fr)));
            float lfm  = stm[j] + logsig;
            float mnew = (stn[j] == 0.f) ? ir : fmaxf(ir, lfm);
            float ig   = expf(ir  - mnew);
            float fg   = expf(lfm - mnew);
            float cnew = fg * stc[j] + ig * tanhf(zr);
            float nnew = fg * stn[j] + ig;
            float og   = 1.f / (1.f + expf(-orr));
            float ynew = og * cnew / nnew;

            stc[j] = cnew;
            stn[j] = nnew;
            stm[j] = mnew;
            ynxt[bb * 1024 + h] = tf32r(ynew);
            yseq[(bb * SS + s) * 1024 + h] = ynew;
        }

        grid_bar();
    }
}

// ---------------------------------------------------------------------------
// fp32 SIMT GEMM (small emb / fc GEMMs).
template<int BM, int BN, int BK, int TM, int TN, bool BT, bool ACC, bool BIAS>
__global__ void __launch_bounds__(256)
gemm_kernel(const float* __restrict__ A, int lda,
            const float* __restrict__ B, int ldb,
            float* __restrict__ C, int ldc,
            const float* __restrict__ bias,
            int K)
{
    constexpr int TX = BN / TN;
    constexpr int TY = BM / TM;
    constexpr int NT = TX * TY;

    __shared__ float As[BK][BM + 4];
    __shared__ float Bs[BK][BN + 4];

    const int tid = threadIdx.x;
    const int tx = tid % TX;
    const int ty = tid / TX;
    const long bm0 = (long)blockIdx.y * BM;
    const long bn0 = (long)blockIdx.x * BN;

    float acc[TM][TN];
#pragma unroll
    for (int i = 0; i < TM; i++)
#pragma unroll
        for (int j = 0; j < TN; j++) acc[i][j] = 0.f;

    for (int k0 = 0; k0 < K; k0 += BK) {
#pragma unroll
        for (int i = tid * 4; i < BM * BK; i += NT * 4) {
            int r  = i / BK;
            int kk = i % BK;
            float4 v = *(const float4*)(A + (bm0 + r) * (long)lda + (k0 + kk));
            As[kk + 0][r] = v.x;
            As[kk + 1][r] = v.y;
            As[kk + 2][r] = v.z;
            As[kk + 3][r] = v.w;
        }
        if (BT) {
#pragma unroll
            for (int i = tid * 4; i < BN * BK; i += NT * 4) {
                int r  = i / BK;
                int kk = i % BK;
                float4 v = *(const float4*)(B + (bn0 + r) * (long)ldb + (k0 + kk));
                Bs[kk + 0][r] = v.x;
                Bs[kk + 1][r] = v.y;
                Bs[kk + 2][r] = v.z;
                Bs[kk + 3][r] = v.w;
            }
        } else {
#pragma unroll
            for (int i = tid * 4; i < BK * BN; i += NT * 4) {
                int kk = i / BN;
                int c  = i % BN;
                float4 v = *(const float4*)(B + (long)(k0 + kk) * ldb + bn0 + c);
                *(float4*)&Bs[kk][c] = v;
            }
        }
        __syncthreads();

#pragma unroll
        for (int kk = 0; kk < BK; kk++) {
            float a[TM], b[TN];
#pragma unroll
            for (int i = 0; i < TM; i += 4)
                *(float4*)&a[i] = *(const float4*)&As[kk][ty * TM + i];
#pragma unroll
            for (int j = 0; j < TN; j += 4)
                *(float4*)&b[j] = *(const float4*)&Bs[kk][tx * TN + j];
#pragma unroll
            for (int i = 0; i < TM; i++)
#pragma unroll
                for (int j = 0; j < TN; j++)
                    acc[i][j] = fmaf(a[i], b[j], acc[i][j]);
        }
        __syncthreads();
    }

#pragma unroll
    for (int i = 0; i < TM; i++) {
        long row = bm0 + ty * TM + i;
#pragma unroll
        for (int j = 0; j < TN; j++) {
            long col = bn0 + tx * TN + j;
            float v = acc[i][j];
            if (BIAS) v += bias[col];
            long off = row * (long)ldc + col;
            if (ACC) v += C[off];
            C[off] = v;
        }
    }
}

// ---------------------------------------------------------------------------
__device__ __forceinline__ void block_reduce2(float& s, float& ss)
{
    __shared__ float sh[16];
    int lane = threadIdx.x & 31;
    int wid  = threadIdx.x >> 5;
#pragma unroll
    for (int o = 16; o > 0; o >>= 1) {
        s  += __shfl_xor_sync(0xFFFFFFFFu, s,  o);
        ss += __shfl_xor_sync(0xFFFFFFFFu, ss, o);
    }
    if (lane == 0) { sh[wid] = s; sh[8 + wid] = ss; }
    __syncthreads();
    if (threadIdx.x < 32) {
        float a = (lane < 8) ? sh[lane]     : 0.f;
        float b = (lane < 8) ? sh[8 + lane] : 0.f;
#pragma unroll
        for (int o = 4; o > 0; o >>= 1) {
            a += __shfl_xor_sync(0xFFFFFFFFu, a, o);
            b += __shfl_xor_sync(0xFFFFFFFFu, b, o);
        }
        if (lane == 0) { sh[0] = a; sh[8] = b; }
    }
    __syncthreads();
    s  = sh[0];
    ss = sh[8];
}

template<bool ROUND>
__global__ void ln_kernel(const float* __restrict__ x, size_t xs,
                          const float* __restrict__ w,
                          float* __restrict__ out, size_t os)
{
    const float* xr = x + (size_t)blockIdx.x * xs;
    float v[4];
    float s = 0.f, ss = 0.f;
#pragma unroll
    for (int i = 0; i < 4; i++) {
        int c = threadIdx.x + i * 256;
        v[i] = xr[c];
        s  += v[i];
        ss += v[i] * v[i];
    }
    block_reduce2(s, ss);
    float mu  = s * (1.f / 1024.f);
    float var = fmaxf(ss * (1.f / 1024.f) - mu * mu, 0.f);
    float rs  = rsqrtf(var + 1e-5f);
    float* orow = out + (size_t)blockIdx.x * os;
#pragma unroll
    for (int i = 0; i < 4; i++) {
        int c = threadIdx.x + i * 256;
        float o = (v[i] - mu) * rs * w[c];
        orow[c] = ROUND ? tf32r(o) : o;
    }
}

__global__ void ln_add_kernel(const float* __restrict__ y,
                              const float* __restrict__ w,
                              float* __restrict__ h)
{
    const float* yr = y + (size_t)blockIdx.x * HH;
    float v[4];
    float s = 0.f, ss = 0.f;
#pragma unroll
    for (int i = 0; i < 4; i++) {
        int c = threadIdx.x + i * 256;
        v[i] = yr[c];
        s  += v[i];
        ss += v[i] * v[i];
    }
    block_reduce2(s, ss);
    float mu  = s * (1.f / 1024.f);
    float var = fmaxf(ss * (1.f / 1024.f) - mu * mu, 0.f);
    float rs  = rsqrtf(var + 1e-5f);
    float* hrow = h + (size_t)blockIdx.x * HH;
#pragma unroll
    for (int i = 0; i < 4; i++) {
        int c = threadIdx.x + i * 256;
        hrow[c] += (v[i] - mu) * rs * w[c];
    }
}

// ---------------------------------------------------------------------------
__global__ void conv_silu_kernel(const float* __restrict__ xn,
                                 const float* __restrict__ cw,
                                 const float* __restrict__ cb,
                                 float* __restrict__ xc)
{
    size_t idx = (size_t)blockIdx.x * blockDim.x + threadIdx.x; // < NTOK*H
    int h = (int)(idx & 1023);
    size_t t = idx >> 10;
    int s = (int)(t % SS);
    float4 wv = *(const float4*)(cw + (size_t)h * 4);
    float w[4] = {wv.x, wv.y, wv.z, wv.w};
    float acc = cb[h];
#pragma unroll
    for (int k = 0; k < 4; k++) {
        int sp = s - 3 + k;
        if (sp >= 0) {
            long off = (long)idx + (long)(k - 3) * HH;
            acc = fmaf(xn[off], w[k], acc);
        }
    }
    xc[idx] = tf32r(acc / (1.f + expf(-acc)));
}

// ---------------------------------------------------------------------------
__global__ void actmul_inplace_kernel(float* __restrict__ gv)
{
    size_t idx = (size_t)blockIdx.x * blockDim.x + threadIdx.x; // < NTOK*U
    size_t r = idx / UU;
    int    u = (int)(idx - r * UU);
    size_t off = r * U2 + u;
    float g = gv[off];
    float v = gv[off + UU];
    float ge = 0.5f * g * (1.f + erff(g * 0.7071067811865476f));
    gv[off] = tf32r(ge * v);
}

// ---------------------------------------------------------------------------
// One-shot weight prep: tf32-round + reorganize into scratch.
__global__ void prep_weights(const float* __restrict__ Wi,
                             const float* __restrict__ Wf,
                             const float* __restrict__ Wz,
                             const float* __restrict__ Wo,
                             const float* __restrict__ R,
                             const float* __restrict__ up,
                             const float* __restrict__ dn,
                             float* __restrict__ dst)
{
    size_t i = (size_t)blockIdx.x * 256 + threadIdx.x;
    if (i >= W_TOT) return;
    const size_t HHHH = (size_t)HH * HH;
    float v;
    if (i < W_IFS) {
        size_t l = i / (2 * HHHH), r = i % (2 * HHHH);
        v = (r < HHHH ? Wi : Wf)[l * HHHH + (r % HHHH)];
    } else if (i < 2 * W_IFS) {
        size_t j = i - W_IFS;
        size_t l = j / (2 * HHHH), r = j % (2 * HHHH);
        v = (r < HHHH ? Wz : Wo)[l * HHHH + (r % HHHH)];
    } else if (i < 2 * W_IFS + W_R) {
        v = R[i - 2 * W_IFS];
    } else if (i < 2 * W_IFS + W_R + W_UP) {
        v = up[i - 2 * W_IFS - W_R];
    } else {
        v = dn[i - 2 * W_IFS - W_R - W_UP];
    }
    dst[i] = tf32r(v);
}

// ---------------------------------------------------------------------------
extern "C" void kernel_launch(void* const* d_in, const int* in_sizes, int n_in,
                              void* d_out, int out_size)
{
    (void)in_sizes; (void)n_in; (void)out_size;

    const float* x      = (const float*)d_in[0];
    const float* emb_w  = (const float*)d_in[1];
    const float* emb_b  = (const float*)d_in[2];
    const float* conv_w = (const float*)d_in[3];
    const float* conv_b = (const float*)d_in[4];
    const float* Wi     = (const float*)d_in[5];
    const float* Wf     = (const float*)d_in[6];
    const float* Wz     = (const float*)d_in[7];
    const float* Wo     = (const float*)d_in[8];
    const float* R      = (const float*)d_in[9];
    const float* cell_b = (const float*)d_in[10];
    const float* gn_w   = (const float*)d_in[11];
    const float* ln1_w  = (const float*)d_in[12];
    const float* ln2_w  = (const float*)d_in[13];
    const float* ff_up  = (const float*)d_in[14];
    const float* ff_dn  = (const float*)d_in[15];
    const float* post_w = (const float*)d_in[16];
    const float* fc_w   = (const float*)d_in[17];
    const float* fc_b   = (const float*)d_in[18];
    float* out = (float*)d_out;

    float* S_;
    cudaGetSymbolAddress((void**)&S_, g_scratch);
    float* g_h    = S_;
    float* g_xn   = g_h    + (size_t)NTOK * HH;
    float* g_xc   = g_xn   + (size_t)NTOK * HH;   // aliases yseq
    float* g_Wx   = g_xc   + (size_t)NTOK * HH;   // aliases gv
    float* g_raw  = g_Wx   + (size_t)NTOK * H4;   // reused: ybuf0/ybuf1
    float* g_st   = g_raw  + (size_t)BB * H4;
    float* g_last = g_st   + (size_t)4 * BB * HH;
    float* g_w    = g_last + (size_t)BB * HH;

    float* w_if = g_w;
    float* w_zo = w_if + W_IFS;
    float* w_r  = w_zo + W_IFS;
    float* w_up = w_r  + W_R;
    float* w_dn = w_up + W_UP;

    float* g_yseq = g_xc;   // alias
    float* g_gv   = g_Wx;   // alias
    float* g_yb0  = g_raw;
    float* g_yb1  = g_raw + (size_t)BB * HH;

    // scan kernel needs >48KB dynamic smem
    const int SCAN_SMEM = (2 * 64 * 36 + 2 * 32 * 132) * 4;  // 52224 B
    cudaFuncSetAttribute(scan_kernel,
                         cudaFuncAttributeMaxDynamicSharedMemorySize, SCAN_SMEM);

    // one-shot weight prep (tf32 round + stacking)
    prep_weights<<<(unsigned)((W_TOT + 255) / 256), 256>>>(
        Wi, Wf, Wz, Wo, R, ff_up, ff_dn, g_w);

    // h = x @ emb_w^T + emb_b  (small K=128; fp32 SIMT)
    gemm_kernel<128,128,16,8,8,true,false,true>
        <<<dim3(HH/128, NTOK/128), 256>>>(x, II, emb_w, II, g_h, HH, emb_b, II);

    for (int l = 0; l < LL; l++) {
        // xn = LN(h)*ln1_w  (tf32-rounded)
        ln_kernel<true><<<NTOK, 256>>>(g_h, HH, ln1_w + (size_t)l*HH, g_xn, HH);
        // xc = silu(causal_conv(xn))  (tf32-rounded)
        conv_silu_kernel<<<(NTOK*HH)/256, 256>>>(g_xn,
            conv_w + (size_t)l*HH*KK, conv_b + (size_t)l*HH, g_xc);

        // Wx cols [0,2048) = [i|f] = xc @ [Wi;Wf]^T
        gemm_tf32_kernel<false>
            <<<dim3(2048/128, NTOK/128), 256>>>(g_xc, HH,
                                                w_if + (size_t)l*2*HH*HH, HH,
                                                g_Wx, H4, HH);
        // Wx cols [2048,4096) = [z|o] = xn @ [Wz;Wo]^T
        gemm_tf32_kernel<false>
            <<<dim3(2048/128, NTOK/128), 256>>>(g_xn, HH,
                                                w_zo + (size_t)l*2*HH*HH, HH,
                                                g_Wx + 2048, H4, HH);

        // persistent fused scan: all 100 steps in one launch
        scan_kernel<<<SC_CTAS, 256, SCAN_SMEM>>>(
            g_Wx, w_r + (size_t)l*HH*H4, cell_b + (size_t)l*H4,
            g_yb0, g_yb1, g_yseq);

        // h += LN(yseq)*gn_w
        ln_add_kernel<<<NTOK, 256>>>(g_yseq, gn_w + (size_t)l*HH, g_h);

        // FFN
        ln_kernel<true><<<NTOK, 256>>>(g_h, HH, ln2_w + (size_t)l*HH, g_xn, HH);
        gemm_tf32_kernel<false>
            <<<dim3(U2/128, NTOK/128), 256>>>(g_xn, HH,
                                              w_up + (size_t)l*U2*HH, HH,
                                              g_gv, U2, HH);
        actmul_inplace_kernel<<<(NTOK*UU)/256, 256>>>(g_gv);
        gemm_tf32_kernel<true>
            <<<dim3(HH/128, NTOK/128), 256>>>(g_gv, U2,
                                              w_dn + (size_t)l*HH*UU, UU,
                                              g_h, HH, UU);
    }

    // post-LN only needed for last timestep
    ln_kernel<false><<<BB, 256>>>(g_h + (size_t)(SS-1)*HH, (size_t)SS*HH,
                                  post_w, g_last, HH);
    // out = last @ fc_w^T + fc_b
    gemm_kernel<64,128,16,4,8,true,false,true>
        <<<dim3(OO/128, BB/64), 256>>>(g_last, HH, fc_w, HH,
                                       out, OO, fc_b, HH);
}

// round 6
// speedup vs baseline: 3.0929x; 1.0643x over previous
#include <cuda_runtime.h>
#include <cuda_bf16.h>
#include <cstddef>
#include <cstdint>

// Problem constants
#define BB   256
#define SS   100
#define II   128
#define HH   1024
#define OO   128
#define LL   2
#define UU   1344
#define KK   4
#define NTOK (BB * SS)          // 25600
#define H4   (4 * HH)           // 4096
#define U2   (2 * UU)           // 2688

// Scratch layout (floats), with aliasing (see round-4 notes):
#define W_IFS  ((size_t)LL * 2 * HH * HH)   // 4,194,304
#define W_R    ((size_t)LL * HH * H4)       // 8,388,608
#define W_UP   ((size_t)LL * U2 * HH)       // 5,505,024 (g/v row-interleaved)
#define W_DN   ((size_t)LL * HH * UU)       // 2,752,512
#define W_TOT  (2 * W_IFS + W_R + W_UP + W_DN)
#define SCRATCH_FLOATS (185860096ULL + W_TOT)
__device__ float g_scratch[SCRATCH_FLOATS];

// grid barrier state for persistent scan kernel
__device__ unsigned g_bar_cnt = 0;
__device__ unsigned g_bar_phase = 0;

// ---------------------------------------------------------------------------
__device__ __forceinline__ float tf32r(float x)
{
    uint32_t u;
    asm("cvt.rna.tf32.f32 %0, %1;" : "=r"(u) : "f"(x));
    return __uint_as_float(u);
}

__device__ __forceinline__ void cp16(void* s, const void* g)
{
    uint32_t sa = (uint32_t)__cvta_generic_to_shared(s);
    asm volatile("cp.async.cg.shared.global [%0], [%1], 16;\n" :: "r"(sa), "l"(g));
}
__device__ __forceinline__ void cp_commit()
{
    asm volatile("cp.async.commit_group;\n" ::);
}
template<int N>
__device__ __forceinline__ void cp_wait()
{
    asm volatile("cp.async.wait_group %0;\n" :: "n"(N));
}

__device__ __forceinline__ void mma_tf32(float* d, const uint32_t* a, const uint32_t* b)
{
    asm volatile(
        "mma.sync.aligned.m16n8k8.row.col.f32.tf32.tf32.f32 "
        "{%0,%1,%2,%3},{%4,%5,%6,%7},{%8,%9},{%0,%1,%2,%3};"
        : "+f"(d[0]), "+f"(d[1]), "+f"(d[2]), "+f"(d[3])
        : "r"(a[0]), "r"(a[1]), "r"(a[2]), "r"(a[3]),
          "r"(b[0]), "r"(b[1]));
}

#define LDSM4(r0, r1, r2, r3, addr) \
    asm volatile("ldmatrix.sync.aligned.m8n8.x4.shared.b16 {%0,%1,%2,%3}, [%4];" \
                 : "=r"(r0), "=r"(r1), "=r"(r2), "=r"(r3) : "r"(addr))

__device__ __forceinline__ float gelu_exact(float g)
{
    return 0.5f * g * (1.f + erff(g * 0.7071067811865476f));
}

// ---------------------------------------------------------------------------
// tf32 tensor-core GEMM.  C[M,N] = A[M,K] * B^T (+C if ACC), B stored [N,K].
// 128x128x16 tiles, 256 threads, 4-stage cp.async pipeline, ldmatrix frags.
// GELU: treats adjacent col pairs as (g,v); writes gelu(g)*v (tf32-rounded)
// into half-width C (ldc = N/2).
template<bool ACC, bool BIAS, bool GELU>
__global__ void __launch_bounds__(256)
gemm_tf32_kernel(const float* __restrict__ A, int lda,
                 const float* __restrict__ B, int ldb,
                 float* __restrict__ C, int ldc,
                 const float* __restrict__ bias, int K)
{
    constexpr int BM = 128, BK = 16, STR = 20, S = 4;
    extern __shared__ float sm[];
    float* As = sm;                       // [S][128][20]
    float* Bs = sm + S * BM * STR;        // [S][128][20]

    const int tid  = threadIdx.x;
    const int lane = tid & 31;
    const int warp = tid >> 5;
    const int wm = (warp >> 2) * 64;
    const int wn = (warp & 3) * 32;
    const int lr = lane >> 2;
    const int lc = lane & 3;
    const long bm0 = (long)blockIdx.y * BM;
    const long bn0 = (long)blockIdx.x * 128;

    // ldmatrix per-lane offsets
    const int a_row = (lane & 7) + ((lane >> 3) & 1) * 8;
    const int a_col = (lane >> 4) * 4;
    const int b_row = (lane & 7) + (lane >> 4) * 8;
    const int b_col = ((lane >> 3) & 1) * 4;
    const uint32_t as_base = (uint32_t)__cvta_generic_to_shared(As);
    const uint32_t bs_base = (uint32_t)__cvta_generic_to_shared(Bs);

    float acc[4][4][4];
#pragma unroll
    for (int mi = 0; mi < 4; mi++)
#pragma unroll
        for (int ni = 0; ni < 4; ni++)
#pragma unroll
            for (int t = 0; t < 4; t++) acc[mi][ni][t] = 0.f;

    auto prefetch = [&](int s, int k0) {
        float* as = As + s * BM * STR;
        float* bs = Bs + s * BM * STR;
#pragma unroll
        for (int j = 0; j < 2; j++) {
            int i = tid + j * 256;
            int row = i >> 2, kp = (i & 3) * 4;
            cp16(as + row * STR + kp, A + (bm0 + row) * (long)lda + k0 + kp);
        }
#pragma unroll
        for (int j = 0; j < 2; j++) {
            int i = tid + j * 256;
            int row = i >> 2, kp = (i & 3) * 4;
            cp16(bs + row * STR + kp, B + (bn0 + row) * (long)ldb + k0 + kp);
        }
    };

    auto compute = [&](int s) {
#pragma unroll
        for (int kk = 0; kk < BK; kk += 8) {
            uint32_t a[4][4], b[4][2];
#pragma unroll
            for (int mi = 0; mi < 4; mi++) {
                uint32_t addr = as_base +
                    ((s * BM + wm + mi * 16 + a_row) * STR + kk + a_col) * 4;
                LDSM4(a[mi][0], a[mi][1], a[mi][2], a[mi][3], addr);
            }
#pragma unroll
            for (int np = 0; np < 2; np++) {
                uint32_t addr = bs_base +
                    ((s * BM + wn + np * 16 + b_row) * STR + kk + b_col) * 4;
                LDSM4(b[2 * np][0], b[2 * np][1], b[2 * np + 1][0], b[2 * np + 1][1], addr);
            }
#pragma unroll
            for (int mi = 0; mi < 4; mi++)
#pragma unroll
                for (int ni = 0; ni < 4; ni++)
                    mma_tf32(acc[mi][ni], a[mi], b[ni]);
        }
    };

    const int NIT = K / BK;
#pragma unroll
    for (int s = 0; s < S - 1; s++) {
        if (s < NIT) prefetch(s, s * BK);
        cp_commit();
    }
    for (int it = 0; it < NIT; ++it) {
        cp_wait<S - 2>();
        __syncthreads();
        int nf = it + S - 1;
        if (nf < NIT) prefetch(nf % S, nf * BK);
        cp_commit();
        compute(it % S);
    }

    // Epilogue
#pragma unroll
    for (int mi = 0; mi < 4; mi++) {
        long r0 = bm0 + wm + mi * 16 + lr;
#pragma unroll
        for (int ni = 0; ni < 4; ni++) {
            int c0l = wn + ni * 8 + lc * 2;
            long c0 = bn0 + c0l;
            if (GELU) {
                long j = c0 >> 1;
                C[r0 * (long)ldc + j] =
                    tf32r(gelu_exact(acc[mi][ni][0]) * acc[mi][ni][1]);
                C[(r0 + 8) * (long)ldc + j] =
                    tf32r(gelu_exact(acc[mi][ni][2]) * acc[mi][ni][3]);
            } else {
                float2* p0 = (float2*)(C + r0 * (long)ldc + c0);
                float2* p1 = (float2*)(C + (r0 + 8) * (long)ldc + c0);
                float b0 = 0.f, b1 = 0.f;
                if (BIAS) { b0 = bias[c0]; b1 = bias[c0 + 1]; }
                if (ACC) {
                    float2 v0 = *p0, v1 = *p1;
                    v0.x += acc[mi][ni][0] + b0; v0.y += acc[mi][ni][1] + b1;
                    v1.x += acc[mi][ni][2] + b0; v1.y += acc[mi][ni][3] + b1;
                    *p0 = v0; *p1 = v1;
                } else {
                    *p0 = make_float2(acc[mi][ni][0] + b0, acc[mi][ni][1] + b1);
                    *p1 = make_float2(acc[mi][ni][2] + b0, acc[mi][ni][3] + b1);
                }
            }
        }
    }
}

// ---------------------------------------------------------------------------
// Persistent fused sLSTM scan kernel.
#define SC_CTAS 128

__device__ __forceinline__ void grid_bar()
{
    __syncthreads();
    __threadfence();
    if (threadIdx.x == 0) {
        unsigned p = *((volatile unsigned*)&g_bar_phase);
        unsigned my = atomicAdd(&g_bar_cnt, 1u);
        if (my == SC_CTAS - 1) {
            g_bar_cnt = 0;
            __threadfence();
            atomicAdd(&g_bar_phase, 1u);
        } else {
            while (*((volatile unsigned*)&g_bar_phase) == p) { }
        }
    }
    __syncthreads();
    __threadfence();
}

__global__ void __launch_bounds__(256)
scan_kernel(const float* __restrict__ Wx, const float* __restrict__ Rw,
            const float* __restrict__ cb,
            float* __restrict__ yb0, float* __restrict__ yb1,
            float* __restrict__ yseq)
{
    extern __shared__ float sm[];
    constexpr int ASTR = 36, BSTR = 132, BK = 32, RSTR = 132;
    float* As   = sm;                    // [2][64][36]
    float* Bs   = sm + 2 * 64 * ASTR;    // [2][32][132]
    float* rawS = sm;                    // [64][132] (aliases)

    const int tid  = threadIdx.x;
    const int lane = tid & 31;
    const int warp = tid >> 5;
    const int wm = (warp >> 2) * 32;
    const int wn = (warp & 3) * 32;
    const int lr = lane >> 2;
    const int lc = lane & 3;
    const int mt = blockIdx.x >> 5;
    const int ht = blockIdx.x & 31;

    const int hl = tid & 31;
    const int rg = tid >> 5;
    const int h  = ht * 32 + hl;
    const long acol = (long)mt * 64;

    float cbv[4];
#pragma unroll
    for (int g = 0; g < 4; g++) cbv[g] = cb[g * 1024 + h];

    float stc[8], stn[8], stm[8];
#pragma unroll
    for (int j = 0; j < 8; j++) { stc[j] = 0.f; stn[j] = 0.f; stm[j] = 0.f; }

    {
        float4 z = make_float4(0.f, 0.f, 0.f, 0.f);
        float* p = yb0 + (size_t)blockIdx.x * 2048 + tid * 8;
        *(float4*)p = z;
        *(float4*)(p + 4) = z;
    }
    grid_bar();

    for (int s = 0; s < SS; s++) {
        const float* ycur = (s & 1) ? yb1 : yb0;
        float*       ynxt = (s & 1) ? yb0 : yb1;

        float acc[2][4][4];
#pragma unroll
        for (int mi = 0; mi < 2; mi++)
#pragma unroll
            for (int ni = 0; ni < 4; ni++)
#pragma unroll
                for (int t = 0; t < 4; t++) acc[mi][ni][t] = 0.f;

        auto prefetch = [&](int buf, int k0) {
#pragma unroll
            for (int j = 0; j < 2; j++) {
                int i = tid + j * 256;
                int row = i >> 3, kp = (i & 7) * 4;
                cp16(&As[(buf * 64 + row) * ASTR + kp],
                     ycur + (acol + row) * 1024 + k0 + kp);
            }
#pragma unroll
            for (int j = 0; j < 4; j++) {
                int i = tid + j * 256;
                int kr = i >> 5, c4 = (i & 31) * 4;
                int g = c4 >> 5, u = c4 & 31;
                cp16(&Bs[(buf * 32 + kr) * BSTR + c4],
                     Rw + (long)(k0 + kr) * 4096 + g * 1024 + ht * 32 + u);
            }
        };

        auto compute = [&](int buf) {
#pragma unroll
            for (int kk = 0; kk < BK; kk += 8) {
                uint32_t a[2][4], b[4][2];
#pragma unroll
                for (int mi = 0; mi < 2; mi++) {
                    int m0 = wm + mi * 16;
                    a[mi][0] = __float_as_uint(As[(buf * 64 + m0 + lr) * ASTR + kk + lc]);
                    a[mi][1] = __float_as_uint(As[(buf * 64 + m0 + 8 + lr) * ASTR + kk + lc]);
                    a[mi][2] = __float_as_uint(As[(buf * 64 + m0 + lr) * ASTR + kk + 4 + lc]);
                    a[mi][3] = __float_as_uint(As[(buf * 64 + m0 + 8 + lr) * ASTR + kk + 4 + lc]);
                }
#pragma unroll
                for (int ni = 0; ni < 4; ni++) {
                    int n0 = wn + ni * 8;
                    b[ni][0] = __float_as_uint(Bs[(buf * 32 + kk + lc) * BSTR + n0 + lr]);
                    b[ni][1] = __float_as_uint(Bs[(buf * 32 + kk + 4 + lc) * BSTR + n0 + lr]);
                }
#pragma unroll
                for (int mi = 0; mi < 2; mi++)
#pragma unroll
                    for (int ni = 0; ni < 4; ni++)
                        mma_tf32(acc[mi][ni], a[mi], b[ni]);
            }
        };

        constexpr int NIT = 1024 / BK;
        prefetch(0, 0);
        cp_commit();
        for (int it = 0; it < NIT; ++it) {
            if (it + 1 < NIT) {
                prefetch((it + 1) & 1, (it + 1) * BK);
                cp_commit();
                cp_wait<1>();
            } else {
                cp_wait<0>();
            }
            __syncthreads();
            compute(it & 1);
            __syncthreads();
        }

#pragma unroll
        for (int mi = 0; mi < 2; mi++) {
            int r0 = wm + mi * 16 + lr;
#pragma unroll
            for (int ni = 0; ni < 4; ni++) {
                int c0 = wn + ni * 8 + lc * 2;
                *(float2*)&rawS[r0 * RSTR + c0] =
                    make_float2(acc[mi][ni][0], acc[mi][ni][1]);
                *(float2*)&rawS[(r0 + 8) * RSTR + c0] =
                    make_float2(acc[mi][ni][2], acc[mi][ni][3]);
            }
        }
        __syncthreads();

#pragma unroll
        for (int j = 0; j < 8; j++) {
            int row = rg * 8 + j;
            long bb = acol + row;
            const float* wx = Wx + ((bb * SS + s) << 12) + h;

            float ir  = rawS[row * RSTR + hl]      + wx[0]    + cbv[0];
            float fr  = rawS[row * RSTR + 32 + hl] + wx[1024] + cbv[1];
            float zr  = rawS[row * RSTR + 64 + hl] + wx[2048] + cbv[2];
            float orr = rawS[row * RSTR + 96 + hl] + wx[3072] + cbv[3];

            float logsig = (fr >= 0.f) ? -log1pf(__expf(-fr))
                                       : (fr - log1pf(__expf(fr)));
            float lfm  = stm[j] + logsig;
            float mnew = (stn[j] == 0.f) ? ir : fmaxf(ir, lfm);
            float ig   = __expf(ir  - mnew);
            float fg   = __expf(lfm - mnew);
            float ez   = __expf(-2.f * fabsf(zr));
            float tz   = copysignf((1.f - ez) / (1.f + ez), zr);
            float cnew = fg * stc[j] + ig * tz;
            float nnew = fg * stn[j] + ig;
            float og   = 1.f / (1.f + __expf(-orr));
            float ynew = og * cnew / nnew;

            stc[j] = cnew;
            stn[j] = nnew;
            stm[j] = mnew;
            ynxt[bb * 1024 + h] = tf32r(ynew);
            yseq[(bb * SS + s) * 1024 + h] = ynew;
        }

        grid_bar();
    }
}

// ---------------------------------------------------------------------------
// fp32 SIMT GEMM (fc only).
template<int BM, int BN, int BK, int TM, int TN, bool BT, bool ACC, bool BIAS>
__global__ void __launch_bounds__(256)
gemm_kernel(const float* __restrict__ A, int lda,
            const float* __restrict__ B, int ldb,
            float* __restrict__ C, int ldc,
            const float* __restrict__ bias,
            int K)
{
    constexpr int TX = BN / TN;
    constexpr int TY = BM / TM;
    constexpr int NT = TX * TY;

    __shared__ float As[BK][BM + 4];
    __shared__ float Bs[BK][BN + 4];

    const int tid = threadIdx.x;
    const int tx = tid % TX;
    const int ty = tid / TX;
    const long bm0 = (long)blockIdx.y * BM;
    const long bn0 = (long)blockIdx.x * BN;

    float acc[TM][TN];
#pragma unroll
    for (int i = 0; i < TM; i++)
#pragma unroll
        for (int j = 0; j < TN; j++) acc[i][j] = 0.f;

    for (int k0 = 0; k0 < K; k0 += BK) {
#pragma unroll
        for (int i = tid * 4; i < BM * BK; i += NT * 4) {
            int r  = i / BK;
            int kk = i % BK;
            float4 v = *(const float4*)(A + (bm0 + r) * (long)lda + (k0 + kk));
            As[kk + 0][r] = v.x;
            As[kk + 1][r] = v.y;
            As[kk + 2][r] = v.z;
            As[kk + 3][r] = v.w;
        }
        if (BT) {
#pragma unroll
            for (int i = tid * 4; i < BN * BK; i += NT * 4) {
                int r  = i / BK;
                int kk = i % BK;
                float4 v = *(const float4*)(B + (bn0 + r) * (long)ldb + (k0 + kk));
                Bs[kk + 0][r] = v.x;
                Bs[kk + 1][r] = v.y;
                Bs[kk + 2][r] = v.z;
                Bs[kk + 3][r] = v.w;
            }
        } else {
#pragma unroll
            for (int i = tid * 4; i < BK * BN; i += NT * 4) {
                int kk = i / BN;
                int c  = i % BN;
                float4 v = *(const float4*)(B + (long)(k0 + kk) * ldb + bn0 + c);
                *(float4*)&Bs[kk][c] = v;
            }
        }
        __syncthreads();

#pragma unroll
        for (int kk = 0; kk < BK; kk++) {
            float a[TM], b[TN];
#pragma unroll
            for (int i = 0; i < TM; i += 4)
                *(float4*)&a[i] = *(const float4*)&As[kk][ty * TM + i];
#pragma unroll
            for (int j = 0; j < TN; j += 4)
                *(float4*)&b[j] = *(const float4*)&Bs[kk][tx * TN + j];
#pragma unroll
            for (int i = 0; i < TM; i++)
#pragma unroll
                for (int j = 0; j < TN; j++)
                    acc[i][j] = fmaf(a[i], b[j], acc[i][j]);
        }
        __syncthreads();
    }

#pragma unroll
    for (int i = 0; i < TM; i++) {
        long row = bm0 + ty * TM + i;
#pragma unroll
        for (int j = 0; j < TN; j++) {
            long col = bn0 + tx * TN + j;
            float v = acc[i][j];
            if (BIAS) v += bias[col];
            long off = row * (long)ldc + col;
            if (ACC) v += C[off];
            C[off] = v;
        }
    }
}

// ---------------------------------------------------------------------------
// Warp-per-row LayerNorm kernels (1024 wide). 8 rows per 256-thread block.
__device__ __forceinline__ void warp_reduce2(float& s, float& ss)
{
#pragma unroll
    for (int o = 16; o > 0; o >>= 1) {
        s  += __shfl_xor_sync(0xFFFFFFFFu, s,  o);
        ss += __shfl_xor_sync(0xFFFFFFFFu, ss, o);
    }
}

template<bool ROUND>
__global__ void ln_warp_kernel(const float* __restrict__ x, size_t xs,
                               const float* __restrict__ w,
                               float* __restrict__ out, size_t os)
{
    int warp = threadIdx.x >> 5, lane = threadIdx.x & 31;
    size_t row = (size_t)blockIdx.x * 8 + warp;
    const float* xr = x + row * xs;
    float4 v[8];
    float s = 0.f, ss = 0.f;
#pragma unroll
    for (int i = 0; i < 8; i++) {
        v[i] = *(const float4*)(xr + i * 128 + lane * 4);
        s  += v[i].x + v[i].y + v[i].z + v[i].w;
        ss += v[i].x * v[i].x + v[i].y * v[i].y + v[i].z * v[i].z + v[i].w * v[i].w;
    }
    warp_reduce2(s, ss);
    float mu  = s * (1.f / 1024.f);
    float var = fmaxf(ss * (1.f / 1024.f) - mu * mu, 0.f);
    float rs  = rsqrtf(var + 1e-5f);
    float* orow = out + row * os;
#pragma unroll
    for (int i = 0; i < 8; i++) {
        int c = i * 128 + lane * 4;
        float4 wv = *(const float4*)(w + c);
        float4 o;
        o.x = (v[i].x - mu) * rs * wv.x;
        o.y = (v[i].y - mu) * rs * wv.y;
        o.z = (v[i].z - mu) * rs * wv.z;
        o.w = (v[i].w - mu) * rs * wv.w;
        if (ROUND) {
            o.x = tf32r(o.x); o.y = tf32r(o.y);
            o.z = tf32r(o.z); o.w = tf32r(o.w);
        }
        *(float4*)(orow + c) = o;
    }
}

__global__ void ln_add_warp_kernel(const float* __restrict__ y,
                                   const float* __restrict__ w,
                                   float* __restrict__ h)
{
    int warp = threadIdx.x >> 5, lane = threadIdx.x & 31;
    size_t row = (size_t)blockIdx.x * 8 + warp;
    const float* yr = y + row * HH;
    float4 v[8];
    float s = 0.f, ss = 0.f;
#pragma unroll
    for (int i = 0; i < 8; i++) {
        v[i] = *(const float4*)(yr + i * 128 + lane * 4);
        s  += v[i].x + v[i].y + v[i].z + v[i].w;
        ss += v[i].x * v[i].x + v[i].y * v[i].y + v[i].z * v[i].z + v[i].w * v[i].w;
    }
    warp_reduce2(s, ss);
    float mu  = s * (1.f / 1024.f);
    float var = fmaxf(ss * (1.f / 1024.f) - mu * mu, 0.f);
    float rs  = rsqrtf(var + 1e-5f);
    float* hrow = h + row * HH;
#pragma unroll
    for (int i = 0; i < 8; i++) {
        int c = i * 128 + lane * 4;
        float4 wv = *(const float4*)(w + c);
        float4 hv = *(float4*)(hrow + c);
        hv.x += (v[i].x - mu) * rs * wv.x;
        hv.y += (v[i].y - mu) * rs * wv.y;
        hv.z += (v[i].z - mu) * rs * wv.z;
        hv.w += (v[i].w - mu) * rs * wv.w;
        *(float4*)(hrow + c) = hv;
    }
}

// ---------------------------------------------------------------------------
// Depthwise causal conv (K=4) + SiLU, 4 h-channels per thread, tf32-rounded.
__global__ void conv_silu_kernel(const float* __restrict__ xn,
                                 const float* __restrict__ cw,
                                 const float* __restrict__ cb,
                                 float* __restrict__ xc)
{
    size_t q = (size_t)blockIdx.x * blockDim.x + threadIdx.x; // < NTOK*H/4
    int hq = (int)(q & 255);            // h quad index
    size_t t = q >> 8;                  // token index b*S+s
    int s = (int)(t % SS);
    int h = hq * 4;
    size_t base = t * HH + h;

    float4 w0 = *(const float4*)(cw + (size_t)h * 4);
    float4 w1 = *(const float4*)(cw + (size_t)(h + 1) * 4);
    float4 w2 = *(const float4*)(cw + (size_t)(h + 2) * 4);
    float4 w3 = *(const float4*)(cw + (size_t)(h + 3) * 4);
    float4 bv = *(const float4*)(cb + h);
    float a0 = bv.x, a1 = bv.y, a2 = bv.z, a3 = bv.w;

#pragma unroll
    for (int k = 0; k < 4; k++) {
        int sp = s - 3 + k;
        if (sp >= 0) {
            float4 xv = *(const float4*)(xn + base + (long)(k - 3) * HH);
            a0 = fmaf(xv.x, ((const float*)&w0)[k], a0);
            a1 = fmaf(xv.y, ((const float*)&w1)[k], a1);
            a2 = fmaf(xv.z, ((const float*)&w2)[k], a2);
            a3 = fmaf(xv.w, ((const float*)&w3)[k], a3);
        }
    }
    float4 o;
    o.x = tf32r(a0 / (1.f + __expf(-a0)));
    o.y = tf32r(a1 / (1.f + __expf(-a1)));
    o.z = tf32r(a2 / (1.f + __expf(-a2)));
    o.w = tf32r(a3 / (1.f + __expf(-a3)));
    *(float4*)(xc + base) = o;
}

// ---------------------------------------------------------------------------
// One-shot weight prep: tf32-round + reorganize (ff_up rows g/v-interleaved).
__global__ void prep_weights(const float* __restrict__ Wi,
                             const float* __restrict__ Wf,
                             const float* __restrict__ Wz,
                             const float* __restrict__ Wo,
                             const float* __restrict__ R,
                             const float* __restrict__ up,
                             const float* __restrict__ dn,
                             float* __restrict__ dst)
{
    size_t i = (size_t)blockIdx.x * 256 + threadIdx.x;
    if (i >= W_TOT) return;
    const size_t HHHH = (size_t)HH * HH;
    float v;
    if (i < W_IFS) {
        size_t l = i / (2 * HHHH), r = i % (2 * HHHH);
        v = (r < HHHH ? Wi : Wf)[l * HHHH + (r % HHHH)];
    } else if (i < 2 * W_IFS) {
        size_t j = i - W_IFS;
        size_t l = j / (2 * HHHH), r = j % (2 * HHHH);
        v = (r < HHHH ? Wz : Wo)[l * HHHH + (r % HHHH)];
    } else if (i < 2 * W_IFS + W_R) {
        v = R[i - 2 * W_IFS];
    } else if (i < 2 * W_IFS + W_R + W_UP) {
        size_t j = i - 2 * W_IFS - W_R;
        size_t l = j / ((size_t)U2 * HH);
        size_t rem = j % ((size_t)U2 * HH);
        size_t row = rem / HH, col = rem % HH;
        size_t u = row >> 1, half = row & 1;   // even rows = g, odd = v
        v = up[l * (size_t)U2 * HH + (half * UU + u) * HH + col];
    } else {
        v = dn[i - 2 * W_IFS - W_R - W_UP];
    }
    dst[i] = tf32r(v);
}

// ---------------------------------------------------------------------------
extern "C" void kernel_launch(void* const* d_in, const int* in_sizes, int n_in,
                              void* d_out, int out_size)
{
    (void)in_sizes; (void)n_in; (void)out_size;

    const float* x      = (const float*)d_in[0];
    const float* emb_w  = (const float*)d_in[1];
    const float* emb_b  = (const float*)d_in[2];
    const float* conv_w = (const float*)d_in[3];
    const float* conv_b = (const float*)d_in[4];
    const float* Wi     = (const float*)d_in[5];
    const float* Wf     = (const float*)d_in[6];
    const float* Wz     = (const float*)d_in[7];
    const float* Wo     = (const float*)d_in[8];
    const float* R      = (const float*)d_in[9];
    const float* cell_b = (const float*)d_in[10];
    const float* gn_w   = (const float*)d_in[11];
    const float* ln1_w  = (const float*)d_in[12];
    const float* ln2_w  = (const float*)d_in[13];
    const float* ff_up  = (const float*)d_in[14];
    const float* ff_dn  = (const float*)d_in[15];
    const float* post_w = (const float*)d_in[16];
    const float* fc_w   = (const float*)d_in[17];
    const float* fc_b   = (const float*)d_in[18];
    float* out = (float*)d_out;

    float* S_;
    cudaGetSymbolAddress((void**)&S_, g_scratch);
    float* g_h    = S_;
    float* g_xn   = g_h    + (size_t)NTOK * HH;
    float* g_xc   = g_xn   + (size_t)NTOK * HH;   // aliases yseq
    float* g_Wx   = g_xc   + (size_t)NTOK * HH;   // aliases act
    float* g_raw  = g_Wx   + (size_t)NTOK * H4;   // ybuf0/ybuf1
    float* g_st   = g_raw  + (size_t)BB * H4;
    float* g_last = g_st   + (size_t)4 * BB * HH;
    float* g_w    = g_last + (size_t)BB * HH;

    float* w_if = g_w;
    float* w_zo = w_if + W_IFS;
    float* w_r  = w_zo + W_IFS;
    float* w_up = w_r  + W_R;
    float* w_dn = w_up + W_UP;

    float* g_yseq = g_xc;   // alias
    float* g_act  = g_Wx;   // alias (act [NTOK, UU])
    float* g_yb0  = g_raw;
    float* g_yb1  = g_raw + (size_t)BB * HH;

    const int SCAN_SMEM = (2 * 64 * 36 + 2 * 32 * 132) * 4;  // 52224 B
    const int GEMM_SMEM = 2 * 4 * 128 * 20 * 4;              // 81920 B
    cudaFuncSetAttribute(scan_kernel,
                         cudaFuncAttributeMaxDynamicSharedMemorySize, SCAN_SMEM);
    cudaFuncSetAttribute(gemm_tf32_kernel<false,false,false>,
                         cudaFuncAttributeMaxDynamicSharedMemorySize, GEMM_SMEM);
    cudaFuncSetAttribute(gemm_tf32_kernel<false,true,false>,
                         cudaFuncAttributeMaxDynamicSharedMemorySize, GEMM_SMEM);
    cudaFuncSetAttribute(gemm_tf32_kernel<false,false,true>,
                         cudaFuncAttributeMaxDynamicSharedMemorySize, GEMM_SMEM);
    cudaFuncSetAttribute(gemm_tf32_kernel<true,false,false>,
                         cudaFuncAttributeMaxDynamicSharedMemorySize, GEMM_SMEM);

    // one-shot weight prep
    prep_weights<<<(unsigned)((W_TOT + 255) / 256), 256>>>(
        Wi, Wf, Wz, Wo, R, ff_up, ff_dn, g_w);

    // h = x @ emb_w^T + emb_b  (tf32; operands truncated in HW)
    gemm_tf32_kernel<false,true,false>
        <<<dim3(HH/128, NTOK/128), 256, GEMM_SMEM>>>(x, II, emb_w, II,
                                                     g_h, HH, emb_b, II);

    for (int l = 0; l < LL; l++) {
        // xn = LN(h)*ln1_w  (tf32-rounded)
        ln_warp_kernel<true><<<NTOK/8, 256>>>(g_h, HH, ln1_w + (size_t)l*HH,
                                              g_xn, HH);
        // xc = silu(causal_conv(xn))
        conv_silu_kernel<<<(NTOK*HH/4)/256, 256>>>(g_xn,
            conv_w + (size_t)l*HH*KK, conv_b + (size_t)l*HH, g_xc);

        // Wx cols [0,2048) = [i|f] = xc @ [Wi;Wf]^T
        gemm_tf32_kernel<false,false,false>
            <<<dim3(16, 200), 256, GEMM_SMEM>>>(g_xc, HH,
                                                w_if + (size_t)l*2*HH*HH, HH,
                                                g_Wx, H4, nullptr, HH);
        // Wx cols [2048,4096) = [z|o] = xn @ [Wz;Wo]^T
        gemm_tf32_kernel<false,false,false>
            <<<dim3(16, 200), 256, GEMM_SMEM>>>(g_xn, HH,
                                                w_zo + (size_t)l*2*HH*HH, HH,
                                                g_Wx + 2048, H4, nullptr, HH);

        // persistent fused scan: all 100 steps in one launch
        scan_kernel<<<SC_CTAS, 256, SCAN_SMEM>>>(
            g_Wx, w_r + (size_t)l*HH*H4, cell_b + (size_t)l*H4,
            g_yb0, g_yb1, g_yseq);

        // h += LN(yseq)*gn_w
        ln_add_warp_kernel<<<NTOK/8, 256>>>(g_yseq, gn_w + (size_t)l*HH, g_h);

        // FFN: fn = LN(h)*ln2_w ; act = gelu(g)*v fused in up-GEMM epilogue ;
        //      h += act @ ff_dn^T
        ln_warp_kernel<true><<<NTOK/8, 256>>>(g_h, HH, ln2_w + (size_t)l*HH,
                                              g_xn, HH);
        gemm_tf32_kernel<false,false,true>
            <<<dim3(U2/128, 200), 256, GEMM_SMEM>>>(g_xn, HH,
                                                    w_up + (size_t)l*U2*HH, HH,
                                                    g_act, UU, nullptr, HH);
        gemm_tf32_kernel<true,false,false>
            <<<dim3(8, 200), 256, GEMM_SMEM>>>(g_act, UU,
                                               w_dn + (size_t)l*HH*UU, UU,
                                               g_h, HH, nullptr, UU);
    }

    // post-LN only needed for last timestep
    ln_warp_kernel<false><<<BB/8, 256>>>(g_h + (size_t)(SS-1)*HH, (size_t)SS*HH,
                                         post_w, g_last, HH);
    // out = last @ fc_w^T + fc_b
    gemm_kernel<64,128,16,4,8,true,false,true>
        <<<dim3(OO/128, BB/64), 256>>>(g_last, HH, fc_w, HH,
                                       out, OO, fc_b, HH);
}

// round 10
// speedup vs baseline: 4.8312x; 1.5620x over previous
#include <cuda_runtime.h>
#include <cuda_fp16.h>
#include <cstddef>
#include <cstdint>

// Problem constants
#define BB   256
#define SS   100
#define II   128
#define HH   1024
#define OO   128
#define LL   2
#define UU   1344
#define KK   4
#define NTOK (BB * SS)          // 25600
#define H4   (4 * HH)           // 4096
#define U2   (2 * UU)           // 2688

// ---------------------------------------------------------------------------
// Scratch layout.
// fp32 region (floats): h 26,214,400 | yseq 26,214,400 | last 262,144
// fp16 region (halfs): x_h 3,276,800 | xn_h 26,214,400 | xc_h 26,214,400 |
//   Wx_h 104,857,600 (act_h aliases) | yb 524,288 | w_h 25,165,824
// total = 52,690,944 + 93,126,656 = 145,817,600 floats <= 146,000,000
#define W_IFS  ((size_t)LL * 2 * HH * HH)   // 4,194,304
#define W_RT   ((size_t)LL * H4 * HH)       // 8,388,608 (transposed [l][n][k])
#define W_UP   ((size_t)LL * U2 * HH)       // 5,505,024 (g/v row-interleaved)
#define W_DN   ((size_t)LL * HH * UU)       // 2,752,512
#define W_EMB  ((size_t)HH * II)            // 131,072
#define W_TOT  (2 * W_IFS + W_RT + W_UP + W_DN + W_EMB)
#define PREP_N (W_TOT + (size_t)NTOK * II)  // + x conversion
#define SCRATCH_FLOATS 146000000ULL
__device__ float g_scratch[SCRATCH_FLOATS];

// monotonic grid-barrier counter for persistent scan kernel (never reset;
// race-free: each arrival spins until the cumulative count reaches the next
// multiple of SC_CTAS above its own ticket).
__device__ unsigned g_bar_cnt = 0;

// ---------------------------------------------------------------------------
__device__ __forceinline__ void cp16(void* s, const void* g)
{
    uint32_t sa = (uint32_t)__cvta_generic_to_shared(s);
    asm volatile("cp.async.cg.shared.global [%0], [%1], 16;\n" :: "r"(sa), "l"(g));
}
__device__ __forceinline__ void cp_commit()
{
    asm volatile("cp.async.commit_group;\n" ::);
}
template<int N>
__device__ __forceinline__ void cp_wait()
{
    asm volatile("cp.async.wait_group %0;\n" :: "n"(N));
}

__device__ __forceinline__ void mma_f16(float* d, const uint32_t* a, const uint32_t* b)
{
    asm volatile(
        "mma.sync.aligned.m16n8k16.row.col.f32.f16.f16.f32 "
        "{%0,%1,%2,%3},{%4,%5,%6,%7},{%8,%9},{%0,%1,%2,%3};"
        : "+f"(d[0]), "+f"(d[1]), "+f"(d[2]), "+f"(d[3])
        : "r"(a[0]), "r"(a[1]), "r"(a[2]), "r"(a[3]),
          "r"(b[0]), "r"(b[1]));
}

#define LDSM4(r0, r1, r2, r3, addr) \
    asm volatile("ldmatrix.sync.aligned.m8n8.x4.shared.b16 {%0,%1,%2,%3}, [%4];" \
                 : "=r"(r0), "=r"(r1), "=r"(r2), "=r"(r3) : "r"(addr))

__device__ __forceinline__ float gelu_exact(float g)
{
    return 0.5f * g * (1.f + erff(g * 0.7071067811865476f));
}

// ---------------------------------------------------------------------------
// fp16 tensor-core GEMM.  C[M,N] = A[M,K] * B^T, B stored [N,K] (halfs).
// 128x128x32 tiles, 256 threads, 4-stage cp.async pipeline, ldmatrix m16n8k16.
// OUTH: C is half. GELU (implies OUTH): adjacent col pairs (g,v) ->
//   gelu(g)*v into half-width C (ldc = N/2). BIAS/ACC: fp32 C paths.
template<bool OUTH, bool ACC, bool BIAS, bool GELU>
__global__ void __launch_bounds__(256)
gemm_f16_kernel(const __half* __restrict__ A, int lda,
                const __half* __restrict__ B, int ldb,
                void* __restrict__ Cv, int ldc,
                const float* __restrict__ bias, int K)
{
    constexpr int BM = 128, BK = 32, STR = 40, S = 4;
    extern __shared__ __half smh[];
    __half* As = smh;                     // [S][128][40]
    __half* Bs = smh + S * BM * STR;      // [S][128][40]

    const int tid  = threadIdx.x;
    const int lane = tid & 31;
    const int warp = tid >> 5;
    const int wm = (warp >> 2) * 64;
    const int wn = (warp & 3) * 32;
    const int lr = lane >> 2;
    const int lc = lane & 3;
    const long bm0 = (long)blockIdx.y * BM;
    const long bn0 = (long)blockIdx.x * 128;

    const int q_row = (lane & 7) + ((lane >> 3) & 1) * 8;
    const int q_col = (lane >> 4) * 8;    // halfs
    const uint32_t as_base = (uint32_t)__cvta_generic_to_shared(As);
    const uint32_t bs_base = (uint32_t)__cvta_generic_to_shared(Bs);

    float acc[4][4][4];
#pragma unroll
    for (int mi = 0; mi < 4; mi++)
#pragma unroll
        for (int ni = 0; ni < 4; ni++)
#pragma unroll
            for (int t = 0; t < 4; t++) acc[mi][ni][t] = 0.f;

    auto prefetch = [&](int s, int k0) {
        __half* as = As + s * BM * STR;
        __half* bs = Bs + s * BM * STR;
#pragma unroll
        for (int j = 0; j < 2; j++) {
            int i = tid + j * 256;
            int row = i >> 2, off = (i & 3) * 8;
            cp16(as + row * STR + off, A + (bm0 + row) * (long)lda + k0 + off);
        }
#pragma unroll
        for (int j = 0; j < 2; j++) {
            int i = tid + j * 256;
            int row = i >> 2, off = (i & 3) * 8;
            cp16(bs + row * STR + off, B + (bn0 + row) * (long)ldb + k0 + off);
        }
    };

    auto compute = [&](int s) {
#pragma unroll
        for (int kk = 0; kk < BK; kk += 16) {
            uint32_t a[4][4], b[4][2];
#pragma unroll
            for (int mi = 0; mi < 4; mi++) {
                uint32_t addr = as_base +
                    ((s * BM + wm + mi * 16 + q_row) * STR + kk + q_col) * 2;
                LDSM4(a[mi][0], a[mi][1], a[mi][2], a[mi][3], addr);
            }
#pragma unroll
            for (int np = 0; np < 2; np++) {
                uint32_t r0, r1, r2, r3;
                uint32_t addr = bs_base +
                    ((s * BM + wn + np * 16 + q_row) * STR + kk + q_col) * 2;
                LDSM4(r0, r1, r2, r3, addr);
                b[2 * np][0] = r0; b[2 * np + 1][0] = r1;
                b[2 * np][1] = r2; b[2 * np + 1][1] = r3;
            }
#pragma unroll
            for (int mi = 0; mi < 4; mi++)
#pragma unroll
                for (int ni = 0; ni < 4; ni++)
                    mma_f16(acc[mi][ni], a[mi], b[ni]);
        }
    };

    const int NIT = K / BK;
#pragma unroll
    for (int s = 0; s < S - 1; s++) {
        if (s < NIT) prefetch(s, s * BK);
        cp_commit();
    }
    for (int it = 0; it < NIT; ++it) {
        cp_wait<S - 2>();
        __syncthreads();
        int nf = it + S - 1;
        if (nf < NIT) prefetch(nf % S, nf * BK);
        cp_commit();
        compute(it % S);
    }

    // Epilogue
#pragma unroll
    for (int mi = 0; mi < 4; mi++) {
        long r0 = bm0 + wm + mi * 16 + lr;
#pragma unroll
        for (int ni = 0; ni < 4; ni++) {
            long c0 = bn0 + wn + ni * 8 + lc * 2;
            if (GELU) {
                __half* C = (__half*)Cv;
                long j = c0 >> 1;
                C[r0 * (long)ldc + j] =
                    __float2half(gelu_exact(acc[mi][ni][0]) * acc[mi][ni][1]);
                C[(r0 + 8) * (long)ldc + j] =
                    __float2half(gelu_exact(acc[mi][ni][2]) * acc[mi][ni][3]);
            } else if (OUTH) {
                __half* C = (__half*)Cv;
                *(__half2*)(C + r0 * (long)ldc + c0) =
                    __floats2half2_rn(acc[mi][ni][0], acc[mi][ni][1]);
                *(__half2*)(C + (r0 + 8) * (long)ldc + c0) =
                    __floats2half2_rn(acc[mi][ni][2], acc[mi][ni][3]);
            } else {
                float* C = (float*)Cv;
                float2* p0 = (float2*)(C + r0 * (long)ldc + c0);
                float2* p1 = (float2*)(C + (r0 + 8) * (long)ldc + c0);
                float b0 = 0.f, b1 = 0.f;
                if (BIAS) { b0 = bias[c0]; b1 = bias[c0 + 1]; }
                if (ACC) {
                    float2 v0 = *p0, v1 = *p1;
                    v0.x += acc[mi][ni][0] + b0; v0.y += acc[mi][ni][1] + b1;
                    v1.x += acc[mi][ni][2] + b0; v1.y += acc[mi][ni][3] + b1;
                    *p0 = v0; *p1 = v1;
                } else {
                    *p0 = make_float2(acc[mi][ni][0] + b0, acc[mi][ni][1] + b1);
                    *p1 = make_float2(acc[mi][ni][2] + b0, acc[mi][ni][3] + b1);
                }
            }
        }
    }
}

// ---------------------------------------------------------------------------
// Persistent fused sLSTM scan kernel, fp16 GEMM (m16n8k16).
// 128 CTAs: (mt = bid>>5 in [0,4): 64 batch rows; ht = bid&31: 32 h).
// B = Rt [n][k] rows gathered per ht. State (c,n,m) fp32 in registers;
// y fp16 double-buffered in scratch.
#define SC_CTAS 128

// Race-free monotonic grid barrier: each CTA takes a ticket; the barrier
// epoch a ticket belongs to is my/SC_CTAS; release when the global count
// reaches the end of that epoch. No reset, no phase word, no stale-arrival
// hazard. Counter persists across launches/replays (monotonic, wrap-safe for
// any realistic replay count).
__device__ __forceinline__ void grid_bar()
{
    __syncthreads();
    __threadfence();
    if (threadIdx.x == 0) {
        unsigned my = atomicAdd(&g_bar_cnt, 1u);
        unsigned target = (my / SC_CTAS + 1u) * SC_CTAS;
        while (*((volatile unsigned*)&g_bar_cnt) < target) { }
    }
    __syncthreads();
    __threadfence();
}

__global__ void __launch_bounds__(256)
scan_kernel(const __half* __restrict__ Wx, const __half* __restrict__ Rt,
            const float* __restrict__ cb,
            __half* __restrict__ yb0, __half* __restrict__ yb1,
            float* __restrict__ yseq)
{
    extern __shared__ __half smh[];
    constexpr int STR = 40, BK = 32, RSTR = 132;
    __half* As = smh;                     // [2][64][40]  =  5,120 halfs
    __half* Bs = smh + 2 * 64 * STR;      // [2][128][40] = 10,240 halfs
    float*  rawS = (float*)smh;           // [64][132] fp32 = 33,792 B (aliases
                                          //  As/Bs after GEMM; smem sized for it)

    const int tid  = threadIdx.x;
    const int lane = tid & 31;
    const int warp = tid >> 5;
    const int wm = (warp >> 2) * 32;      // 2 m-warps x 32
    const int wn = (warp & 3) * 32;       // 4 n-warps x 32
    const int lr = lane >> 2;
    const int lc = lane & 3;
    const int mt = blockIdx.x >> 5;
    const int ht = blockIdx.x & 31;

    const int q_row = (lane & 7) + ((lane >> 3) & 1) * 8;
    const int q_col = (lane >> 4) * 8;
    const uint32_t as_base = (uint32_t)__cvta_generic_to_shared(As);
    const uint32_t bs_base = (uint32_t)__cvta_generic_to_shared(Bs);

    const int hl = tid & 31;
    const int rg = tid >> 5;
    const int h  = ht * 32 + hl;
    const long acol = (long)mt * 64;

    float cbv[4];
#pragma unroll
    for (int g = 0; g < 4; g++) cbv[g] = cb[g * 1024 + h];

    float stc[8], stn[8], stm[8];
#pragma unroll
    for (int j = 0; j < 8; j++) { stc[j] = 0.f; stn[j] = 0.f; stm[j] = 0.f; }

    // zero this CTA's slice of yb0 (2048 halfs = 256 threads x 16B)
    {
        uint4 z = make_uint4(0u, 0u, 0u, 0u);
        *(uint4*)(yb0 + (size_t)blockIdx.x * 2048 + tid * 8) = z;
    }
    grid_bar();

    for (int s = 0; s < SS; s++) {
        const __half* ycur = (s & 1) ? yb1 : yb0;
        __half*       ynxt = (s & 1) ? yb0 : yb1;

        float acc[2][4][4];
#pragma unroll
        for (int mi = 0; mi < 2; mi++)
#pragma unroll
            for (int ni = 0; ni < 4; ni++)
#pragma unroll
                for (int t = 0; t < 4; t++) acc[mi][ni][t] = 0.f;

        auto prefetch = [&](int buf, int k0) {
            // A: 64 rows x 32 halfs = 256 chunks (1/thread)
            {
                int row = tid >> 2, off = (tid & 3) * 8;
                cp16(&As[(buf * 64 + row) * STR + off],
                     ycur + (acol + row) * 1024 + k0 + off);
            }
            // B: 128 gathered n-rows x 32 halfs = 512 chunks (2/thread)
#pragma unroll
            for (int j = 0; j < 2; j++) {
                int i = tid + j * 256;
                int nt = i >> 2, off = (i & 3) * 8;
                long nglob = (long)(nt >> 5) * 1024 + ht * 32 + (nt & 31);
                cp16(&Bs[(buf * 128 + nt) * STR + off],
                     Rt + nglob * 1024 + k0 + off);
            }
        };

        auto compute = [&](int buf) {
#pragma unroll
            for (int kk = 0; kk < BK; kk += 16) {
                uint32_t a[2][4], b[4][2];
#pragma unroll
                for (int mi = 0; mi < 2; mi++) {
                    uint32_t addr = as_base +
                        ((buf * 64 + wm + mi * 16 + q_row) * STR + kk + q_col) * 2;
                    LDSM4(a[mi][0], a[mi][1], a[mi][2], a[mi][3], addr);
                }
#pragma unroll
                for (int np = 0; np < 2; np++) {
                    uint32_t r0, r1, r2, r3;
                    uint32_t addr = bs_base +
                        ((buf * 128 + wn + np * 16 + q_row) * STR + kk + q_col) * 2;
                    LDSM4(r0, r1, r2, r3, addr);
                    b[2 * np][0] = r0; b[2 * np + 1][0] = r1;
                    b[2 * np][1] = r2; b[2 * np + 1][1] = r3;
                }
#pragma unroll
                for (int mi = 0; mi < 2; mi++)
#pragma unroll
                    for (int ni = 0; ni < 4; ni++)
                        mma_f16(acc[mi][ni], a[mi], b[ni]);
            }
        };

        constexpr int NIT = 1024 / BK;   // 32
        prefetch(0, 0);
        cp_commit();
        for (int it = 0; it < NIT; ++it) {
            if (it + 1 < NIT) {
                prefetch((it + 1) & 1, (it + 1) * BK);
                cp_commit();
                cp_wait<1>();
            } else {
                cp_wait<0>();
            }
            __syncthreads();
            compute(it & 1);
            __syncthreads();
        }

        // stage raw tile to smem (aliases As/Bs; GEMM done)
#pragma unroll
        for (int mi = 0; mi < 2; mi++) {
            int r0 = wm + mi * 16 + lr;
#pragma unroll
            for (int ni = 0; ni < 4; ni++) {
                int c0 = wn + ni * 8 + lc * 2;
                *(float2*)&rawS[r0 * RSTR + c0] =
                    make_float2(acc[mi][ni][0], acc[mi][ni][1]);
                *(float2*)&rawS[(r0 + 8) * RSTR + c0] =
                    make_float2(acc[mi][ni][2], acc[mi][ni][3]);
            }
        }
        __syncthreads();

        // fused gate update: 8 (b,h) pairs per thread, state in registers
#pragma unroll
        for (int j = 0; j < 8; j++) {
            int row = rg * 8 + j;
            long bb = acol + row;
            const __half* wx = Wx + ((bb * SS + s) << 12) + h;

            float ir  = rawS[row * RSTR + hl]      + __half2float(wx[0])    + cbv[0];
            float fr  = rawS[row * RSTR + 32 + hl] + __half2float(wx[1024]) + cbv[1];
            float zr  = rawS[row * RSTR + 64 + hl] + __half2float(wx[2048]) + cbv[2];
            float orr = rawS[row * RSTR + 96 + hl] + __half2float(wx[3072]) + cbv[3];

            float logsig = (fr >= 0.f) ? -log1pf(__expf(-fr))
                                       : (fr - log1pf(__expf(fr)));
            float lfm  = stm[j] + logsig;
            float mnew = (stn[j] == 0.f) ? ir : fmaxf(ir, lfm);
            float ig   = __expf(ir  - mnew);
            float fg   = __expf(lfm - mnew);
            float ez   = __expf(-2.f * fabsf(zr));
            float tz   = copysignf((1.f - ez) / (1.f + ez), zr);
            float cnew = fg * stc[j] + ig * tz;
            float nnew = fg * stn[j] + ig;
            float og   = 1.f / (1.f + __expf(-orr));
            float ynew = og * cnew / nnew;

            stc[j] = cnew;
            stn[j] = nnew;
            stm[j] = mnew;
            ynxt[bb * 1024 + h] = __float2half(ynew);
            yseq[(bb * SS + s) * 1024 + h] = ynew;
        }

        grid_bar();
    }
}

// ---------------------------------------------------------------------------
// fp32 SIMT GEMM (fc only).
template<int BM, int BN, int BK, int TM, int TN>
__global__ void __launch_bounds__(256)
gemm_fc_kernel(const float* __restrict__ A, int lda,
               const float* __restrict__ B, int ldb,
               float* __restrict__ C, int ldc,
               const float* __restrict__ bias, int K)
{
    constexpr int TX = BN / TN;
    constexpr int TY = BM / TM;
    constexpr int NT = TX * TY;

    __shared__ float As[BK][BM + 4];
    __shared__ float Bs[BK][BN + 4];

    const int tid = threadIdx.x;
    const int tx = tid % TX;
    const int ty = tid / TX;
    const long bm0 = (long)blockIdx.y * BM;
    const long bn0 = (long)blockIdx.x * BN;

    float acc[TM][TN];
#pragma unroll
    for (int i = 0; i < TM; i++)
#pragma unroll
        for (int j = 0; j < TN; j++) acc[i][j] = 0.f;

    for (int k0 = 0; k0 < K; k0 += BK) {
#pragma unroll
        for (int i = tid * 4; i < BM * BK; i += NT * 4) {
            int r = i / BK, kk = i % BK;
            float4 v = *(const float4*)(A + (bm0 + r) * (long)lda + (k0 + kk));
            As[kk + 0][r] = v.x; As[kk + 1][r] = v.y;
            As[kk + 2][r] = v.z; As[kk + 3][r] = v.w;
        }
#pragma unroll
        for (int i = tid * 4; i < BN * BK; i += NT * 4) {
            int r = i / BK, kk = i % BK;
            float4 v = *(const float4*)(B + (bn0 + r) * (long)ldb + (k0 + kk));
            Bs[kk + 0][r] = v.x; Bs[kk + 1][r] = v.y;
            Bs[kk + 2][r] = v.z; Bs[kk + 3][r] = v.w;
        }
        __syncthreads();

#pragma unroll
        for (int kk = 0; kk < BK; kk++) {
            float a[TM], b[TN];
#pragma unroll
            for (int i = 0; i < TM; i += 4)
                *(float4*)&a[i] = *(const float4*)&As[kk][ty * TM + i];
#pragma unroll
            for (int j = 0; j < TN; j += 4)
                *(float4*)&b[j] = *(const float4*)&Bs[kk][tx * TN + j];
#pragma unroll
            for (int i = 0; i < TM; i++)
#pragma unroll
                for (int j = 0; j < TN; j++)
                    acc[i][j] = fmaf(a[i], b[j], acc[i][j]);
        }
        __syncthreads();
    }

#pragma unroll
    for (int i = 0; i < TM; i++) {
        long row = bm0 + ty * TM + i;
#pragma unroll
        for (int j = 0; j < TN; j++) {
            long col = bn0 + tx * TN + j;
            C[row * (long)ldc + col] = acc[i][j] + bias[col];
        }
    }
}

// ---------------------------------------------------------------------------
__device__ __forceinline__ void warp_reduce2(float& s, float& ss)
{
#pragma unroll
    for (int o = 16; o > 0; o >>= 1) {
        s  += __shfl_xor_sync(0xFFFFFFFFu, s,  o);
        ss += __shfl_xor_sync(0xFFFFFFFFu, ss, o);
    }
}

// out = LN(x)*w ; OUTH: write halfs, else floats. Warp-per-row (1024 wide).
template<bool OUTH>
__global__ void ln_warp_kernel(const float* __restrict__ x, size_t xs,
                               const float* __restrict__ w,
                               void* __restrict__ outv, size_t os)
{
    int warp = threadIdx.x >> 5, lane = threadIdx.x & 31;
    size_t row = (size_t)blockIdx.x * 8 + warp;
    const float* xr = x + row * xs;
    float4 v[8];
    float s = 0.f, ss = 0.f;
#pragma unroll
    for (int i = 0; i < 8; i++) {
        v[i] = *(const float4*)(xr + i * 128 + lane * 4);
        s  += v[i].x + v[i].y + v[i].z + v[i].w;
        ss += v[i].x * v[i].x + v[i].y * v[i].y + v[i].z * v[i].z + v[i].w * v[i].w;
    }
    warp_reduce2(s, ss);
    float mu  = s * (1.f / 1024.f);
    float var = fmaxf(ss * (1.f / 1024.f) - mu * mu, 0.f);
    float rs  = rsqrtf(var + 1e-5f);
#pragma unroll
    for (int i = 0; i < 8; i++) {
        int c = i * 128 + lane * 4;
        float4 wv = *(const float4*)(w + c);
        float o0 = (v[i].x - mu) * rs * wv.x;
        float o1 = (v[i].y - mu) * rs * wv.y;
        float o2 = (v[i].z - mu) * rs * wv.z;
        float o3 = (v[i].w - mu) * rs * wv.w;
        if (OUTH) {
            __half2* op = (__half2*)((__half*)outv + row * os + c);
            op[0] = __floats2half2_rn(o0, o1);
            op[1] = __floats2half2_rn(o2, o3);
        } else {
            *(float4*)((float*)outv + row * os + c) = make_float4(o0, o1, o2, o3);
        }
    }
}

// Fused: h += LN(yseq)*gn ; fn = LN(h_new)*ln2 (half out). Warp-per-row.
__global__ void lnadd_ln2_kernel(const float* __restrict__ yseq,
                                 const float* __restrict__ gn,
                                 const float* __restrict__ ln2,
                                 float* __restrict__ h,
                                 __half* __restrict__ fn)
{
    int warp = threadIdx.x >> 5, lane = threadIdx.x & 31;
    size_t row = (size_t)blockIdx.x * 8 + warp;
    const float* yr = yseq + row * HH;
    float* hr = h + row * HH;
    float4 v[8], hv[8];
    float s = 0.f, ss = 0.f;
#pragma unroll
    for (int i = 0; i < 8; i++) {
        v[i] = *(const float4*)(yr + i * 128 + lane * 4);
        s  += v[i].x + v[i].y + v[i].z + v[i].w;
        ss += v[i].x * v[i].x + v[i].y * v[i].y + v[i].z * v[i].z + v[i].w * v[i].w;
    }
    warp_reduce2(s, ss);
    float mu  = s * (1.f / 1024.f);
    float var = fmaxf(ss * (1.f / 1024.f) - mu * mu, 0.f);
    float rs  = rsqrtf(var + 1e-5f);
    float s2 = 0.f, ss2 = 0.f;
#pragma unroll
    for (int i = 0; i < 8; i++) {
        int c = i * 128 + lane * 4;
        float4 gv = *(const float4*)(gn + c);
        hv[i] = *(float4*)(hr + c);
        hv[i].x += (v[i].x - mu) * rs * gv.x;
        hv[i].y += (v[i].y - mu) * rs * gv.y;
        hv[i].z += (v[i].z - mu) * rs * gv.z;
        hv[i].w += (v[i].w - mu) * rs * gv.w;
        *(float4*)(hr + c) = hv[i];
        s2  += hv[i].x + hv[i].y + hv[i].z + hv[i].w;
        ss2 += hv[i].x * hv[i].x + hv[i].y * hv[i].y
             + hv[i].z * hv[i].z + hv[i].w * hv[i].w;
    }
    warp_reduce2(s2, ss2);
    float mu2  = s2 * (1.f / 1024.f);
    float var2 = fmaxf(ss2 * (1.f / 1024.f) - mu2 * mu2, 0.f);
    float rs2  = rsqrtf(var2 + 1e-5f);
#pragma unroll
    for (int i = 0; i < 8; i++) {
        int c = i * 128 + lane * 4;
        float4 wv = *(const float4*)(ln2 + c);
        __half2* op = (__half2*)(fn + row * HH + c);
        op[0] = __floats2half2_rn((hv[i].x - mu2) * rs2 * wv.x,
                                  (hv[i].y - mu2) * rs2 * wv.y);
        op[1] = __floats2half2_rn((hv[i].z - mu2) * rs2 * wv.z,
                                  (hv[i].w - mu2) * rs2 * wv.w);
    }
}

// ---------------------------------------------------------------------------
// Depthwise causal conv (K=4) + SiLU; fp16 in/out, fp32 math.
__global__ void conv_silu_kernel(const __half* __restrict__ xn,
                                 const float* __restrict__ cw,
                                 const float* __restrict__ cb,
                                 __half* __restrict__ xc)
{
    size_t q = (size_t)blockIdx.x * blockDim.x + threadIdx.x; // < NTOK*H/4
    int hq = (int)(q & 255);
    size_t t = q >> 8;
    int s = (int)(t % SS);
    int h = hq * 4;
    size_t base = t * HH + h;

    float4 w0 = *(const float4*)(cw + (size_t)h * 4);
    float4 w1 = *(const float4*)(cw + (size_t)(h + 1) * 4);
    float4 w2 = *(const float4*)(cw + (size_t)(h + 2) * 4);
    float4 w3 = *(const float4*)(cw + (size_t)(h + 3) * 4);
    float4 bv = *(const float4*)(cb + h);
    float a0 = bv.x, a1 = bv.y, a2 = bv.z, a3 = bv.w;

#pragma unroll
    for (int k = 0; k < 4; k++) {
        int sp = s - 3 + k;
        if (sp >= 0) {
            const __half2* xp = (const __half2*)(xn + base + (long)(k - 3) * HH);
            float2 x01 = __half22float2(xp[0]);
            float2 x23 = __half22float2(xp[1]);
            a0 = fmaf(x01.x, ((const float*)&w0)[k], a0);
            a1 = fmaf(x01.y, ((const float*)&w1)[k], a1);
            a2 = fmaf(x23.x, ((const float*)&w2)[k], a2);
            a3 = fmaf(x23.y, ((const float*)&w3)[k], a3);
        }
    }
    __half2* op = (__half2*)(xc + base);
    op[0] = __floats2half2_rn(a0 / (1.f + __expf(-a0)), a1 / (1.f + __expf(-a1)));
    op[1] = __floats2half2_rn(a2 / (1.f + __expf(-a2)), a3 / (1.f + __expf(-a3)));
}

// ---------------------------------------------------------------------------
// One-shot prep: convert all weights to fp16 (stack i/f and z/o, transpose R
// to [n][k], interleave ff_up g/v rows, copy emb_w) and convert x to fp16.
__global__ void prep_kernel(const float* __restrict__ Wi,
                            const float* __restrict__ Wf,
                            const float* __restrict__ Wz,
                            const float* __restrict__ Wo,
                            const float* __restrict__ R,
                            const float* __restrict__ up,
                            const float* __restrict__ dn,
                            const float* __restrict__ embw,
                            const float* __restrict__ x,
                            __half* __restrict__ wdst,
                            __half* __restrict__ xdst)
{
    size_t i = (size_t)blockIdx.x * 256 + threadIdx.x;
    if (i >= PREP_N) return;
    const size_t HHHH = (size_t)HH * HH;
    if (i >= W_TOT) {                      // x conversion
        size_t j = i - W_TOT;
        xdst[j] = __float2half(x[j]);
        return;
    }
    float v;
    if (i < W_IFS) {
        size_t l = i / (2 * HHHH), r = i % (2 * HHHH);
        v = (r < HHHH ? Wi : Wf)[l * HHHH + (r % HHHH)];
    } else if (i < 2 * W_IFS) {
        size_t j = i - W_IFS;
        size_t l = j / (2 * HHHH), r = j % (2 * HHHH);
        v = (r < HHHH ? Wz : Wo)[l * HHHH + (r % HHHH)];
    } else if (i < 2 * W_IFS + W_RT) {
        size_t j = i - 2 * W_IFS;
        size_t l = j / ((size_t)H4 * HH);
        size_t rem = j % ((size_t)H4 * HH);
        size_t n = rem / HH, k = rem % HH;       // dst [n][k]
        v = R[l * (size_t)HH * H4 + k * H4 + n]; // src [k][n]
    } else if (i < 2 * W_IFS + W_RT + W_UP) {
        size_t j = i - 2 * W_IFS - W_RT;
        size_t l = j / ((size_t)U2 * HH);
        size_t rem = j % ((size_t)U2 * HH);
        size_t row = rem / HH, col = rem % HH;
        size_t u = row >> 1, half = row & 1;     // even rows = g, odd = v
        v = up[l * (size_t)U2 * HH + (half * UU + u) * HH + col];
    } else if (i < 2 * W_IFS + W_RT + W_UP + W_DN) {
        v = dn[i - 2 * W_IFS - W_RT - W_UP];
    } else {
        v = embw[i - 2 * W_IFS - W_RT - W_UP - W_DN];
    }
    wdst[i] = __float2half(v);
}

// ---------------------------------------------------------------------------
extern "C" void kernel_launch(void* const* d_in, const int* in_sizes, int n_in,
                              void* d_out, int out_size)
{
    (void)in_sizes; (void)n_in; (void)out_size;

    const float* x      = (const float*)d_in[0];
    const float* emb_w  = (const float*)d_in[1];
    const float* emb_b  = (const float*)d_in[2];
    const float* conv_w = (const float*)d_in[3];
    const float* conv_b = (const float*)d_in[4];
    const float* Wi     = (const float*)d_in[5];
    const float* Wf     = (const float*)d_in[6];
    const float* Wz     = (const float*)d_in[7];
    const float* Wo     = (const float*)d_in[8];
    const float* R      = (const float*)d_in[9];
    const float* cell_b = (const float*)d_in[10];
    const float* gn_w   = (const float*)d_in[11];
    const float* ln1_w  = (const float*)d_in[12];
    const float* ln2_w  = (const float*)d_in[13];
    const float* ff_up  = (const float*)d_in[14];
    const float* ff_dn  = (const float*)d_in[15];
    const float* post_w = (const float*)d_in[16];
    const float* fc_w   = (const float*)d_in[17];
    const float* fc_b   = (const float*)d_in[18];
    float* out = (float*)d_out;

    float* S_;
    cudaGetSymbolAddress((void**)&S_, g_scratch);
    float* g_h    = S_;
    float* g_yseq = g_h    + (size_t)NTOK * HH;
    float* g_last = g_yseq + (size_t)NTOK * HH;
    __half* H_    = (__half*)(g_last + (size_t)BB * HH);

    __half* x_h  = H_;
    __half* xn_h = x_h  + (size_t)NTOK * II;
    __half* xc_h = xn_h + (size_t)NTOK * HH;
    __half* Wx_h = xc_h + (size_t)NTOK * HH;    // act_h aliases
    __half* yb0  = Wx_h + (size_t)NTOK * H4;
    __half* yb1  = yb0  + (size_t)BB * HH;
    __half* w_h  = yb1  + (size_t)BB * HH;

    __half* w_if  = w_h;
    __half* w_zo  = w_if + W_IFS;
    __half* w_rt  = w_zo + W_IFS;
    __half* w_up  = w_rt + W_RT;
    __half* w_dn  = w_up + W_UP;
    __half* w_emb = w_dn + W_DN;
    __half* act_h = Wx_h;   // alias

    // scan smem must cover BOTH the fp16 GEMM tiles (30,720 B) and the
    // fp32 rawS staging region [64][132]*4 = 33,792 B that aliases them.
    const int SCAN_SMEM = 64 * 132 * 4;                      // 33,792 B
    const int GEMM_SMEM = 2 * 4 * 128 * 40 * 2;              // 81,920 B
    cudaFuncSetAttribute(gemm_f16_kernel<true,false,false,false>,
                         cudaFuncAttributeMaxDynamicSharedMemorySize, GEMM_SMEM);
    cudaFuncSetAttribute(gemm_f16_kernel<true,false,false,true>,
                         cudaFuncAttributeMaxDynamicSharedMemorySize, GEMM_SMEM);
    cudaFuncSetAttribute(gemm_f16_kernel<false,false,true,false>,
                         cudaFuncAttributeMaxDynamicSharedMemorySize, GEMM_SMEM);
    cudaFuncSetAttribute(gemm_f16_kernel<false,true,false,false>,
                         cudaFuncAttributeMaxDynamicSharedMemorySize, GEMM_SMEM);

    // 0: one-shot conversions
    prep_kernel<<<(unsigned)((PREP_N + 255) / 256), 256>>>(
        Wi, Wf, Wz, Wo, R, ff_up, ff_dn, emb_w, x, w_h, x_h);

    // 1: h = x_h @ emb_w^T + emb_b (fp32 out)
    gemm_f16_kernel<false,false,true,false>
        <<<dim3(HH/128, NTOK/128), 256, GEMM_SMEM>>>(x_h, II, w_emb, II,
                                                     g_h, HH, emb_b, II);

    for (int l = 0; l < LL; l++) {
        // xn = LN(h)*ln1_w  (half out)
        ln_warp_kernel<true><<<NTOK/8, 256>>>(g_h, HH, ln1_w + (size_t)l*HH,
                                              xn_h, HH);
        // Wx cols [2048,4096) = [z|o] = xn @ [Wz;Wo]^T
        gemm_f16_kernel<true,false,false,false>
            <<<dim3(16, 200), 256, GEMM_SMEM>>>(xn_h, HH,
                                                w_zo + (size_t)l*2*HH*HH, HH,
                                                Wx_h + 2048, H4, nullptr, HH);
        // xc = silu(causal_conv(xn))
        conv_silu_kernel<<<(NTOK*HH/4)/256, 256>>>(xn_h,
            conv_w + (size_t)l*HH*KK, conv_b + (size_t)l*HH, xc_h);
        // Wx cols [0,2048) = [i|f] = xc @ [Wi;Wf]^T
        gemm_f16_kernel<true,false,false,false>
            <<<dim3(16, 200), 256, GEMM_SMEM>>>(xc_h, HH,
                                                w_if + (size_t)l*2*HH*HH, HH,
                                                Wx_h, H4, nullptr, HH);

        // persistent fused scan: all 100 steps in one launch
        scan_kernel<<<SC_CTAS, 256, SCAN_SMEM>>>(
            Wx_h, w_rt + (size_t)l*H4*HH, cell_b + (size_t)l*H4,
            yb0, yb1, g_yseq);

        // fused: h += LN(yseq)*gn ; fn = LN(h)*ln2 (half out, into xn_h)
        lnadd_ln2_kernel<<<NTOK/8, 256>>>(g_yseq, gn_w + (size_t)l*HH,
                                          ln2_w + (size_t)l*HH, g_h, xn_h);

        // FFN: act = gelu(g)*v fused in up-GEMM epilogue ; h += act @ ff_dn^T
        gemm_f16_kernel<true,false,false,true>
            <<<dim3(U2/128, 200), 256, GEMM_SMEM>>>(xn_h, HH,
                                                    w_up + (size_t)l*U2*HH, HH,
                                                    act_h, UU, nullptr, HH);
        gemm_f16_kernel<false,true,false,false>
            <<<dim3(8, 200), 256, GEMM_SMEM>>>(act_h, UU,
                                               w_dn + (size_t)l*HH*UU, UU,
                                               g_h, HH, nullptr, UU);
    }

    // post-LN only needed for last timestep (fp32 out)
    ln_warp_kernel<false><<<BB/8, 256>>>(g_h + (size_t)(SS-1)*HH, (size_t)SS*HH,
                                         post_w, g_last, HH);
    // out = last @ fc_w^T + fc_b
    gemm_fc_kernel<64,128,16,4,8>
        <<<dim3(OO/128, BB/64), 256>>>(g_last, HH, fc_w, HH,
                                       out, OO, fc_b, HH);
}